// round 14
// baseline (speedup 1.0000x reference)
#include <cuda_runtime.h>
#include <cuda_fp16.h>
#include <stdint.h>
#include <math.h>

#define NCKG 50000
#define NPSG 10000
#define ECKG 500000
#define EPSG 100000
#define CH 128

// ---------------- scratch (static device memory; no runtime allocation) ----------------
__device__ float g_x0[NCKG * CH];
__device__ float g_x1[NCKG * CH];
__device__ float g_px[NPSG * CH];
__device__ float g_q0[NCKG * CH];
__device__ float g_q1[NCKG * CH];
__device__ float g_pq[NPSG * CH];
__device__ __half g_kv0h[NCKG * 256];
__device__ __half g_kv1h[NCKG * 256];
__device__ __half g_pkvh[NPSG * 256];
__device__ float g_agg0[NCKG * CH];
__device__ float g_agg1[NCKG * CH];
__device__ float g_pagg[NPSG * CH];
__device__ float g_Wc0[CH * 384], g_Wc1[CH * 384], g_pWc[CH * 384];
__device__ float g_bc0[384], g_bc1[384], g_pbc[384];
__device__ int g_deg0[NCKG], g_deg1[NCKG], g_degp[NPSG];
__device__ int g_roff0[NCKG + 1], g_roff1[NCKG + 1], g_roffp[NPSG + 1];
__device__ int g_col0[ECKG], g_col1[ECKG], g_colp[EPSG];
__device__ int g_bs0[64], g_bs1[64], g_bsp[64];
__device__ float g_vec[768]; // [0:128) qv, [128:256) psum, [256:384) fused, [384:512) tsum0, [512:640) tsum1

__device__ __forceinline__ float gelu_exact(float x) {
    return 0.5f * x * (1.0f + erff(x * 0.70710678118654752f));
}
__device__ __forceinline__ uint32_t f2tf32(float x) {
    uint32_t r;
    asm("cvt.rna.tf32.f32 %0, %1;" : "=r"(r) : "f"(x));
    return r;
}
__device__ __forceinline__ void mma_tf32(float* c, const uint32_t* a, const uint32_t* b) {
    asm volatile(
        "mma.sync.aligned.m16n8k8.row.col.f32.tf32.tf32.f32 "
        "{%0,%1,%2,%3}, {%4,%5,%6,%7}, {%8,%9}, {%0,%1,%2,%3};"
        : "+f"(c[0]), "+f"(c[1]), "+f"(c[2]), "+f"(c[3])
        : "r"(a[0]), "r"(a[1]), "r"(a[2]), "r"(a[3]), "r"(b[0]), "r"(b[1]));
}

// padded strides: LDAA % 32 == 4 (A frag loads conflict-free), LDAB % 32 == 8 (B frag loads conflict-free)
#define LDAA 68
#define LDAB 136
// 64-row M-tile: A 64*68*4 + B 64*136*4 = 52224 B -> 3 blocks/SM at <=85 regs
#define SMEM_MMA ((64 * LDAA + 64 * LDAB) * 4)

struct GemmJob {
    const float* A;       // [M,128]
    const float* W;       // [128,N]
    const float* bias;    // [N]
    float* C;             // fp32 out (mode 1/2: [M,N]; mode 3: q out [M,128])
    __half* Ch;           // mode 3: kv half out [M,256]
    const float* skipx;   // mode 2
    int skipidx;          // mode 2
    int M;
};

// ---------------- tensor-core GEMM: out = epilogue((A+fusedA)[M,128] @ W[128,N] + bias) --
// grid = (N/128, ceil(maxM/64), njobs), block = 256 (8 warps: 2 along M x 4 along N, 32x32/warp)
// mode 1: relu ; 2: beta*(..)+(1-beta)*(skipx+fusedSkip) ; 3: qkv split (bn==0 -> fp32 q, else half kv)
__global__ __launch_bounds__(256, 3) void gemm_mma_k(
    GemmJob j0, GemmJob j1, GemmJob j2, int N, int mode,
    const float* __restrict__ skipv,
    const float* __restrict__ fusedA, const float* __restrict__ fusedSkip)
{
    const GemmJob& J = (blockIdx.z == 0) ? j0 : (blockIdx.z == 1) ? j1 : j2;
    const int M = J.M;
    const int bm = blockIdx.y * 64;
    if (bm >= M) return;
    const float* __restrict__ A = J.A;
    const float* __restrict__ W = J.W;
    const float* __restrict__ bias = J.bias;

    extern __shared__ uint32_t sm[];
    uint32_t* As = sm;                // As[row*LDAA + k], 64 rows, k in [0,64)
    uint32_t* Bs = sm + 64 * LDAA;    // Bs[k*LDAB + n]
    const int tid = threadIdx.x;
    const int wid = tid >> 5;
    const int lane = tid & 31;
    const int bn = blockIdx.x * 128;

    const int warp_m = wid & 1;       // 2 M-bands of 32
    const int warp_n = wid >> 1;      // 4 N-bands of 32
    const int g = lane >> 2;
    const int tg = lane & 3;
    const int arow = warp_m * 32 + g;
    const int bcol = warp_n * 32 + g;

    float acc[2][4][4];
#pragma unroll
    for (int t = 0; t < 2; t++)
#pragma unroll
        for (int j = 0; j < 4; j++)
#pragma unroll
            for (int q = 0; q < 4; q++) acc[t][j][q] = 0.f;

#pragma unroll
    for (int s = 0; s < 2; s++) {
        if (s) __syncthreads();
        // stage A half: 64 rows x 64 K
        for (int idx = tid; idx < 64 * 16; idx += 256) {
            int row = idx >> 4;
            int c4 = (idx & 15) * 4;
            int gk = s * 64 + c4;
            float4 v = make_float4(0.f, 0.f, 0.f, 0.f);
            if (bm + row < M) v = *(const float4*)(A + (size_t)(bm + row) * 128 + gk);
            if (fusedA) {
                v.x += fusedA[gk]; v.y += fusedA[gk + 1];
                v.z += fusedA[gk + 2]; v.w += fusedA[gk + 3];
            }
            uint32_t* p = As + row * LDAA + c4;
            p[0] = f2tf32(v.x); p[1] = f2tf32(v.y); p[2] = f2tf32(v.z); p[3] = f2tf32(v.w);
        }
        // stage B half: 64 K x 128 N
        for (int idx = tid; idx < 64 * 32; idx += 256) {
            int k = idx >> 5;
            int n4 = (idx & 31) * 4;
            float4 v = *(const float4*)(W + (size_t)(s * 64 + k) * N + bn + n4);
            uint32_t* p = Bs + k * LDAB + n4;
            p[0] = f2tf32(v.x); p[1] = f2tf32(v.y); p[2] = f2tf32(v.z); p[3] = f2tf32(v.w);
        }
        __syncthreads();
#pragma unroll
        for (int ks = 0; ks < 8; ks++) {
            const int k0 = ks * 8;
            uint32_t a[2][4];
#pragma unroll
            for (int t = 0; t < 2; t++) {
                int r = arow + t * 16;
                a[t][0] = As[r * LDAA + k0 + tg];
                a[t][1] = As[(r + 8) * LDAA + k0 + tg];
                a[t][2] = As[r * LDAA + k0 + tg + 4];
                a[t][3] = As[(r + 8) * LDAA + k0 + tg + 4];
            }
            uint32_t b[4][2];
#pragma unroll
            for (int j = 0; j < 4; j++) {
                b[j][0] = Bs[(k0 + tg) * LDAB + bcol + j * 8];
                b[j][1] = Bs[(k0 + tg + 4) * LDAB + bcol + j * 8];
            }
#pragma unroll
            for (int t = 0; t < 2; t++)
#pragma unroll
                for (int j = 0; j < 4; j++) mma_tf32(acc[t][j], a[t], b[j]);
        }
    }

    // epilogue
    float beta = 1.f, omb = 0.f;
    if (mode == 2) {
        float sv = skipv[J.skipidx];
        beta = 1.f / (1.f + expf(-sv));
        omb = 1.f - beta;
    }
#pragma unroll
    for (int t = 0; t < 2; t++) {
        int row0 = bm + warp_m * 32 + t * 16 + g;
#pragma unroll
        for (int half = 0; half < 2; half++) {
            int row = row0 + half * 8;
            if (row >= M) continue;
#pragma unroll
            for (int j = 0; j < 4; j++) {
                int col = bn + warp_n * 32 + j * 8 + 2 * tg;
                float v0 = acc[t][j][2 * half + 0] + bias[col];
                float v1 = acc[t][j][2 * half + 1] + bias[col + 1];
                if (mode == 1) {
                    v0 = fmaxf(v0, 0.f); v1 = fmaxf(v1, 0.f);
                    *(float2*)(J.C + (size_t)row * N + col) = make_float2(v0, v1);
                } else if (mode == 2) {
                    float sx0 = J.skipx[(size_t)row * 128 + col];
                    float sx1 = J.skipx[(size_t)row * 128 + col + 1];
                    if (fusedSkip) { sx0 += fusedSkip[col]; sx1 += fusedSkip[col + 1]; }
                    v0 = beta * v0 + omb * sx0;
                    v1 = beta * v1 + omb * sx1;
                    *(float2*)(J.C + (size_t)row * N + col) = make_float2(v0, v1);
                } else { // mode 3: qkv split
                    if (bn == 0) {
                        *(float2*)(J.C + (size_t)row * 128 + col) = make_float2(v0, v1);
                    } else {
                        *(half2*)(J.Ch + (size_t)row * 256 + (col - 128)) =
                            __floats2half2_rn(v0, v1);
                    }
                }
            }
        }
    }
}

// ---------------- combined weight build: Wc = [Wq | Wk@krel | Wv@vrel], bc likewise ----
__device__ __forceinline__ void build_wc_body(
    const float* __restrict__ Wkqv, const float* __restrict__ bkqv,
    const float* __restrict__ krel, const float* __restrict__ vrel,
    float* __restrict__ Wc, float* __restrict__ bc, int j, int r)
{
    float val;
    if (j < 128) {
        val = Wkqv[r * 384 + 128 + j];
        if (r == 0) bc[j] = bkqv[128 + j];
    } else if (j < 256) {
        int h = (j - 128) >> 6, e = (j - 128) & 63;
        const float* kr = krel + h * 4096;
        float s = 0.f;
        for (int d = 0; d < 64; d++) s += Wkqv[r * 384 + h * 64 + d] * kr[d * 64 + e];
        val = s;
        if (r == 0) {
            float bs = 0.f;
            for (int d = 0; d < 64; d++) bs += bkqv[h * 64 + d] * kr[d * 64 + e];
            bc[j] = bs;
        }
    } else {
        int h = (j - 256) >> 6, e = (j - 256) & 63;
        const float* vr = vrel + h * 4096;
        float s = 0.f;
        for (int d = 0; d < 64; d++) s += Wkqv[r * 384 + 256 + h * 64 + d] * vr[d * 64 + e];
        val = s;
        if (r == 0) {
            float bs = 0.f;
            for (int d = 0; d < 64; d++) bs += bkqv[256 + h * 64 + d] * vr[d * 64 + e];
            bc[j] = bs;
        }
    }
    Wc[r * 384 + j] = val;
}

__global__ void build_wc2_k(
    const float* __restrict__ Wa, const float* __restrict__ ba,
    const float* __restrict__ ka, const float* __restrict__ va,
    float* __restrict__ Wca, float* __restrict__ bca,
    const float* __restrict__ Wb, const float* __restrict__ bb,
    const float* __restrict__ kb, const float* __restrict__ vb,
    float* __restrict__ Wcb, float* __restrict__ bcb)
{
    if (blockIdx.y == 0)
        build_wc_body(Wa, ba, ka, va, Wca, bca, blockIdx.x, threadIdx.x);
    else
        build_wc_body(Wb, bb, kb, vb, Wcb, bcb, blockIdx.x, threadIdx.x);
}

// ---------------- CSR build (merged launches) ----------------
__global__ void hist3_k(const int* __restrict__ d0, const int* __restrict__ d1,
                        const int* __restrict__ dp,
                        int* __restrict__ deg0, int* __restrict__ deg1, int* __restrict__ degp)
{
    int i = blockIdx.x * blockDim.x + threadIdx.x;
    if (i < ECKG) atomicAdd(&deg0[d0[i]], 1);
    else if (i < 2 * ECKG) atomicAdd(&deg1[d1[i - ECKG]], 1);
    else if (i < 2 * ECKG + EPSG) atomicAdd(&degp[dp[i - 2 * ECKG]], 1);
}

__global__ __launch_bounds__(1024) void scan1_k(
    const int* __restrict__ dg0, int* __restrict__ ex0, int* __restrict__ bs0,
    const int* __restrict__ dg1, int* __restrict__ ex1, int* __restrict__ bs1,
    const int* __restrict__ dgp, int* __restrict__ exp_, int* __restrict__ bsp,
    int nCkg, int nPsg, int nbPsg)
{
    const int* deg; int* ex; int* bsum; int n;
    if (blockIdx.y == 0) { deg = dg0; ex = ex0; bsum = bs0; n = nCkg; }
    else if (blockIdx.y == 1) { deg = dg1; ex = ex1; bsum = bs1; n = nCkg; }
    else { if ((int)blockIdx.x >= nbPsg) return; deg = dgp; ex = exp_; bsum = bsp; n = nPsg; }
    __shared__ int ws[32];
    const int tid = threadIdx.x;
    const int lane = tid & 31, w = tid >> 5;
    const int i = blockIdx.x * 1024 + tid;
    int v = (i < n) ? deg[i] : 0;
    int inc = v;
#pragma unroll
    for (int o = 1; o < 32; o <<= 1) {
        int t = __shfl_up_sync(0xffffffffu, inc, o);
        if (lane >= o) inc += t;
    }
    if (lane == 31) ws[w] = inc;
    __syncthreads();
    if (w == 0) {
        int s = ws[lane];
#pragma unroll
        for (int o = 1; o < 32; o <<= 1) {
            int t = __shfl_up_sync(0xffffffffu, s, o);
            if (lane >= o) s += t;
        }
        ws[lane] = s;
    }
    __syncthreads();
    int exv = ((w == 0) ? 0 : ws[w - 1]) + inc - v;
    if (i < n) ex[i] = exv;
    if (tid == 1023) bsum[blockIdx.x] = exv + v;
}

__global__ void scan2all_k(int* __restrict__ b0, int nb0,
                           int* __restrict__ b1, int nb1,
                           int* __restrict__ b2, int nb2)
{
    if (threadIdx.x != 0) return;
    int* b; int nb;
    if (blockIdx.x == 0) { b = b0; nb = nb0; }
    else if (blockIdx.x == 1) { b = b1; nb = nb1; }
    else { b = b2; nb = nb2; }
    int acc = 0;
    for (int j = 0; j < nb; j++) { int x = b[j]; b[j] = acc; acc += x; }
    b[nb] = acc;
}

__global__ __launch_bounds__(1024) void scan3_k(
    int* __restrict__ ex0, const int* __restrict__ bs0, int* __restrict__ cz0,
    int* __restrict__ ex1, const int* __restrict__ bs1, int* __restrict__ cz1,
    int* __restrict__ exp_, const int* __restrict__ bsp, int* __restrict__ czp,
    int nCkg, int nPsg, int nbCkg, int nbPsg)
{
    int* ex; const int* bsum; int* cz; int n; int nb;
    if (blockIdx.y == 0) { ex = ex0; bsum = bs0; cz = cz0; n = nCkg; nb = nbCkg; }
    else if (blockIdx.y == 1) { ex = ex1; bsum = bs1; cz = cz1; n = nCkg; nb = nbCkg; }
    else { if ((int)blockIdx.x >= nbPsg) return; ex = exp_; bsum = bsp; cz = czp; n = nPsg; nb = nbPsg; }
    int i = blockIdx.x * 1024 + threadIdx.x;
    if (i < n) { ex[i] += bsum[blockIdx.x]; cz[i] = 0; }
    if (i == 0) ex[n] = bsum[nb];
}

__global__ void scatter3_k(
    const int* __restrict__ s0, const int* __restrict__ d0,
    const int* __restrict__ r0, int* __restrict__ c0, int* __restrict__ col0,
    const int* __restrict__ s1, const int* __restrict__ d1,
    const int* __restrict__ r1, int* __restrict__ c1, int* __restrict__ col1,
    const int* __restrict__ sp, const int* __restrict__ dp,
    const int* __restrict__ rp, int* __restrict__ cp, int* __restrict__ colp)
{
    int i = blockIdx.x * blockDim.x + threadIdx.x;
    if (i < ECKG) {
        int d = d0[i];
        col0[r0[d] + atomicAdd(&c0[d], 1)] = s0[i];
    } else if (i < 2 * ECKG) {
        int k = i - ECKG;
        int d = d1[k];
        col1[r1[d] + atomicAdd(&c1[d], 1)] = s1[k];
    } else if (i < 2 * ECKG + EPSG) {
        int k = i - 2 * ECKG;
        int d = dp[k];
        colp[rp[d] + atomicAdd(&cp[d], 1)] = sp[k];
    }
}

// ---------------- edge aggregation (single-pass softmax-weighted sum, warp/dst) --------
__device__ __forceinline__ void edge_node_work(
    const float* __restrict__ qf, const __half* __restrict__ kvh,
    const int* __restrict__ roff, const int* __restrict__ col,
    const float* __restrict__ prel, float* __restrict__ agg, int node, int lane)
{
    const float s0 = prel[0] * 0.125f;
    const float s1 = prel[1] * 0.125f;
    const float2* q2 = (const float2*)(qf + (size_t)node * 128);
    const float2 qa = q2[lane];
    const float2 qb = q2[lane + 32];
    float2 a0 = make_float2(0.f, 0.f), a1 = make_float2(0.f, 0.f);
    float S0 = 0.f, S1 = 0.f;
    const int e0 = roff[node], e1 = roff[node + 1];
    for (int eb = e0; eb < e1; eb += 32) {
        int bat = min(32, e1 - eb);
        int ci = (lane < bat) ? col[eb + lane] : 0;
        int it = 0;
        for (; it + 2 <= bat; it += 2) {
            int sA = __shfl_sync(0xffffffffu, ci, it);
            int sB = __shfl_sync(0xffffffffu, ci, it + 1);
            const half2* kvA = (const half2*)(kvh + (size_t)sA * 256);
            const half2* kvB = (const half2*)(kvh + (size_t)sB * 256);
            float2 k0A = __half22float2(kvA[lane]);
            float2 k1A = __half22float2(kvA[lane + 32]);
            float2 v0A = __half22float2(kvA[lane + 64]);
            float2 v1A = __half22float2(kvA[lane + 96]);
            float2 k0B = __half22float2(kvB[lane]);
            float2 k1B = __half22float2(kvB[lane + 32]);
            float2 v0B = __half22float2(kvB[lane + 64]);
            float2 v1B = __half22float2(kvB[lane + 96]);
            float pA0 = qa.x * k0A.x + qa.y * k0A.y;
            float pA1 = qb.x * k1A.x + qb.y * k1A.y;
            float pB0 = qa.x * k0B.x + qa.y * k0B.y;
            float pB1 = qb.x * k1B.x + qb.y * k1B.y;
#pragma unroll
            for (int o = 16; o; o >>= 1) {
                pA0 += __shfl_xor_sync(0xffffffffu, pA0, o);
                pA1 += __shfl_xor_sync(0xffffffffu, pA1, o);
                pB0 += __shfl_xor_sync(0xffffffffu, pB0, o);
                pB1 += __shfl_xor_sync(0xffffffffu, pB1, o);
            }
            float wA0 = expf(pA0 * s0), wA1 = expf(pA1 * s1);
            float wB0 = expf(pB0 * s0), wB1 = expf(pB1 * s1);
            S0 += wA0 + wB0; S1 += wA1 + wB1;
            a0.x += wA0 * v0A.x + wB0 * v0B.x;
            a0.y += wA0 * v0A.y + wB0 * v0B.y;
            a1.x += wA1 * v1A.x + wB1 * v1B.x;
            a1.y += wA1 * v1A.y + wB1 * v1B.y;
        }
        if (it < bat) {
            int sA = __shfl_sync(0xffffffffu, ci, it);
            const half2* kv = (const half2*)(kvh + (size_t)sA * 256);
            float2 k0 = __half22float2(kv[lane]);
            float2 k1 = __half22float2(kv[lane + 32]);
            float2 v0 = __half22float2(kv[lane + 64]);
            float2 v1 = __half22float2(kv[lane + 96]);
            float p0 = qa.x * k0.x + qa.y * k0.y;
            float p1 = qb.x * k1.x + qb.y * k1.y;
#pragma unroll
            for (int o = 16; o; o >>= 1) {
                p0 += __shfl_xor_sync(0xffffffffu, p0, o);
                p1 += __shfl_xor_sync(0xffffffffu, p1, o);
            }
            float w0 = expf(p0 * s0), w1 = expf(p1 * s1);
            S0 += w0; S1 += w1;
            a0.x += w0 * v0.x; a0.y += w0 * v0.y;
            a1.x += w1 * v1.x; a1.y += w1 * v1.y;
        }
    }
    float i0 = 1.f / (S0 + 1e-16f);
    float i1 = 1.f / (S1 + 1e-16f);
    float2* o = (float2*)(agg + (size_t)node * 128);
    o[lane] = make_float2(gelu_exact(a0.x * i0), gelu_exact(a0.y * i0));
    o[lane + 32] = make_float2(gelu_exact(a1.x * i1), gelu_exact(a1.y * i1));
}

__global__ void edge_agg_k(const float* __restrict__ qf, const __half* __restrict__ kvh,
                           const int* __restrict__ roff, const int* __restrict__ col,
                           const float* __restrict__ prel, float* __restrict__ agg, int Nd)
{
    int warp = (blockIdx.x * blockDim.x + threadIdx.x) >> 5;
    int lane = threadIdx.x & 31;
    if (warp >= Nd) return;
    edge_node_work(qf, kvh, roff, col, prel, agg, warp, lane);
}

__global__ void edge_agg2_k(
    const float* __restrict__ qA, const __half* __restrict__ kvA,
    const int* __restrict__ roffA, const int* __restrict__ colA,
    const float* __restrict__ prelA, float* __restrict__ aggA,
    const float* __restrict__ qB, const __half* __restrict__ kvB,
    const int* __restrict__ roffB, const int* __restrict__ colB,
    const float* __restrict__ prelB, float* __restrict__ aggB, int Nd)
{
    int warp = (blockIdx.x * blockDim.x + threadIdx.x) >> 5;
    int lane = threadIdx.x & 31;
    if (warp < Nd)
        edge_node_work(qA, kvA, roffA, colA, prelA, aggA, warp, lane);
    else if (warp < 2 * Nd)
        edge_node_work(qB, kvB, roffB, colB, prelB, aggB, warp - Nd, lane);
}

// ---------------- small kernels ----------------
__global__ void qv_k(const float* __restrict__ qe, const float* __restrict__ W,
                     const float* __restrict__ b, float* __restrict__ qv)
{
    int c = threadIdx.x;
    float s = 0.f;
    for (int d = 0; d < 768; d++) s += qe[d] * W[d * 128 + c];
    s += b[c];
    qv[c] = fmaxf(s, 0.f);
}

__global__ void colsum2_k(const float* __restrict__ xa, const float* __restrict__ xb,
                          int nrows, float* __restrict__ out)
{
    const float* x = (blockIdx.y == 0) ? xa : xb;
    if (x == nullptr) return;
    int col = threadIdx.x & 127;
    int half = threadIdx.x >> 7;
    long long rbeg = (long long)blockIdx.x * 512 + half;
    long long rend = (long long)(blockIdx.x + 1) * 512;
    if (rend > nrows) rend = nrows;
    float s = 0.f;
    for (long long r = rbeg; r < rend; r += 2) s += x[r * 128 + col];
    atomicAdd(&out[col], s);
}

__global__ void vecadd_k(const float* __restrict__ a, const float* __restrict__ b,
                         float sb, float* __restrict__ o)
{
    int c = threadIdx.x;
    o[c] = a[c] + b[c] * sb;
}

__global__ void vecscale_k(const float* __restrict__ a, float sa, float* __restrict__ o)
{
    int c = threadIdx.x;
    o[c] = a[c] * sa;
}

// ---------------- launch ----------------
extern "C" void kernel_launch(void* const* d_in, const int* in_sizes, int n_in,
                              void* d_out, int out_size)
{
    (void)in_sizes; (void)n_in; (void)out_size;
    const float* ckg_x_dis  = (const float*)d_in[0];
    const float* ckg_x_drug = (const float*)d_in[1];
    const float* psg_x      = (const float*)d_in[2];
    const float* query_emb  = (const float*)d_in[3];
    const float* ckg_lin_W  = (const float*)d_in[4];
    const float* ckg_lin_b  = (const float*)d_in[5];
    const float* psg_lin_W  = (const float*)d_in[6];
    const float* psg_lin_b  = (const float*)d_in[7];
    const float* query_W    = (const float*)d_in[8];
    const float* query_b    = (const float*)d_in[9];
    const float* ckg_Wkqv   = (const float*)d_in[10];
    const float* ckg_bkqv   = (const float*)d_in[11];
    const float* ckg_Wout   = (const float*)d_in[12];
    const float* ckg_bout   = (const float*)d_in[13];
    const float* ckg_skip   = (const float*)d_in[14];
    const float* ckg_krel   = (const float*)d_in[15];
    const float* ckg_vrel   = (const float*)d_in[16];
    const float* ckg_prel   = (const float*)d_in[17];
    const float* psg_Wkqv   = (const float*)d_in[18];
    const float* psg_bkqv   = (const float*)d_in[19];
    const float* psg_Wout   = (const float*)d_in[20];
    const float* psg_bout   = (const float*)d_in[21];
    const float* psg_skip   = (const float*)d_in[22];
    const float* psg_krel   = (const float*)d_in[23];
    const float* psg_vrel   = (const float*)d_in[24];
    const float* psg_prel   = (const float*)d_in[25];
    const int* ei_d2g_src   = (const int*)d_in[26];
    const int* ei_d2g_dst   = (const int*)d_in[27];
    const int* ei_g2d_src   = (const int*)d_in[28];
    const int* ei_g2d_dst   = (const int*)d_in[29];
    const int* psg_src      = (const int*)d_in[30];
    const int* psg_dst      = (const int*)d_in[31];
    float* out = (float*)d_out;

    static int inited = 0;
    static float *p_x0, *p_x1, *p_px, *p_q0, *p_q1, *p_pq;
    static __half *p_kv0h, *p_kv1h, *p_pkvh;
    static float *p_agg0, *p_agg1, *p_pagg;
    static float *p_Wc0, *p_Wc1, *p_pWc, *p_bc0, *p_bc1, *p_pbc, *p_vec;
    static int *p_deg0, *p_deg1, *p_degp, *p_roff0, *p_roff1, *p_roffp;
    static int *p_col0, *p_col1, *p_colp, *p_bs0, *p_bs1, *p_bsp;
    static cudaStream_t s1, s2;
    static cudaEvent_t evFork, evCsr, evOutP[2], evCsJ[2];
    if (!inited) {
        cudaGetSymbolAddress((void**)&p_x0, g_x0);
        cudaGetSymbolAddress((void**)&p_x1, g_x1);
        cudaGetSymbolAddress((void**)&p_px, g_px);
        cudaGetSymbolAddress((void**)&p_q0, g_q0);
        cudaGetSymbolAddress((void**)&p_q1, g_q1);
        cudaGetSymbolAddress((void**)&p_pq, g_pq);
        cudaGetSymbolAddress((void**)&p_kv0h, g_kv0h);
        cudaGetSymbolAddress((void**)&p_kv1h, g_kv1h);
        cudaGetSymbolAddress((void**)&p_pkvh, g_pkvh);
        cudaGetSymbolAddress((void**)&p_agg0, g_agg0);
        cudaGetSymbolAddress((void**)&p_agg1, g_agg1);
        cudaGetSymbolAddress((void**)&p_pagg, g_pagg);
        cudaGetSymbolAddress((void**)&p_Wc0, g_Wc0);
        cudaGetSymbolAddress((void**)&p_Wc1, g_Wc1);
        cudaGetSymbolAddress((void**)&p_pWc, g_pWc);
        cudaGetSymbolAddress((void**)&p_bc0, g_bc0);
        cudaGetSymbolAddress((void**)&p_bc1, g_bc1);
        cudaGetSymbolAddress((void**)&p_pbc, g_pbc);
        cudaGetSymbolAddress((void**)&p_vec, g_vec);
        cudaGetSymbolAddress((void**)&p_deg0, g_deg0);
        cudaGetSymbolAddress((void**)&p_deg1, g_deg1);
        cudaGetSymbolAddress((void**)&p_degp, g_degp);
        cudaGetSymbolAddress((void**)&p_roff0, g_roff0);
        cudaGetSymbolAddress((void**)&p_roff1, g_roff1);
        cudaGetSymbolAddress((void**)&p_roffp, g_roffp);
        cudaGetSymbolAddress((void**)&p_col0, g_col0);
        cudaGetSymbolAddress((void**)&p_col1, g_col1);
        cudaGetSymbolAddress((void**)&p_colp, g_colp);
        cudaGetSymbolAddress((void**)&p_bs0, g_bs0);
        cudaGetSymbolAddress((void**)&p_bs1, g_bs1);
        cudaGetSymbolAddress((void**)&p_bsp, g_bsp);
        cudaFuncSetAttribute(gemm_mma_k, cudaFuncAttributeMaxDynamicSharedMemorySize, SMEM_MMA);
        cudaStreamCreateWithFlags(&s1, cudaStreamNonBlocking);
        cudaStreamCreateWithFlags(&s2, cudaStreamNonBlocking);
        cudaEventCreateWithFlags(&evFork, cudaEventDisableTiming);
        cudaEventCreateWithFlags(&evCsr, cudaEventDisableTiming);
        for (int i = 0; i < 2; i++) {
            cudaEventCreateWithFlags(&evOutP[i], cudaEventDisableTiming);
            cudaEventCreateWithFlags(&evCsJ[i], cudaEventDisableTiming);
        }
        inited = 1;
    }

    const int GB_CKG_M = (NCKG + 63) / 64;   // 782 (64-row M tiles)
    const int GB_PSG_M = (NPSG + 63) / 64;   // 157
    const int NB_CKG = (NCKG + 1023) / 1024; // 49
    const int NB_PSG = (NPSG + 1023) / 1024; // 10
    const int ETOT = 2 * ECKG + EPSG;        // 1.1M
    const float* FZ = nullptr;
    GemmJob JZ = {};

    // ---- fork CSR branch onto s1 ----
    cudaEventRecord(evFork, 0);
    cudaStreamWaitEvent(s1, evFork, 0);

    // ---- s1: full CSR build chain ----
    cudaMemsetAsync(p_deg0, 0, NCKG * sizeof(int), s1);
    cudaMemsetAsync(p_deg1, 0, NCKG * sizeof(int), s1);
    cudaMemsetAsync(p_degp, 0, NPSG * sizeof(int), s1);
    hist3_k<<<(ETOT + 255) / 256, 256, 0, s1>>>(ei_d2g_dst, ei_g2d_dst, psg_dst,
                                                p_deg0, p_deg1, p_degp);
    scan1_k<<<dim3(NB_CKG, 3), 1024, 0, s1>>>(p_deg0, p_roff0, p_bs0, p_deg1, p_roff1, p_bs1,
                                              p_degp, p_roffp, p_bsp, NCKG, NPSG, NB_PSG);
    scan2all_k<<<3, 32, 0, s1>>>(p_bs0, NB_CKG, p_bs1, NB_CKG, p_bsp, NB_PSG);
    scan3_k<<<dim3(NB_CKG, 3), 1024, 0, s1>>>(p_roff0, p_bs0, p_deg0, p_roff1, p_bs1, p_deg1,
                                              p_roffp, p_bsp, p_degp, NCKG, NPSG, NB_CKG, NB_PSG);
    scatter3_k<<<(ETOT + 255) / 256, 256, 0, s1>>>(
        ei_d2g_src, ei_d2g_dst, p_roff0, p_deg0, p_col0,
        ei_g2d_src, ei_g2d_dst, p_roff1, p_deg1, p_col1,
        psg_src, psg_dst, p_roffp, p_degp, p_colp);
    cudaEventRecord(evCsr, s1);

    // ---- s0 (capture stream): projections + PSG tower prep, concurrent with CSR ----
    cudaMemsetAsync(p_vec, 0, 768 * sizeof(float));
    qv_k<<<1, 128>>>(query_emb, query_W, query_b, p_vec);
    {
        GemmJob a = {ckg_x_dis, ckg_lin_W, ckg_lin_b, p_x0, nullptr, nullptr, 0, NCKG};
        GemmJob b = {ckg_x_drug, ckg_lin_W + 128 * 128, ckg_lin_b + 128, p_x1, nullptr, nullptr, 0, NCKG};
        GemmJob c = {psg_x, psg_lin_W, psg_lin_b, p_px, nullptr, nullptr, 0, NPSG};
        gemm_mma_k<<<dim3(1, GB_CKG_M, 3), 256, SMEM_MMA>>>(a, b, c, 128, 1, FZ, FZ, FZ);
    }
    build_wc2_k<<<dim3(384, 1), 128>>>(psg_Wkqv, psg_bkqv, psg_krel, psg_vrel, p_pWc, p_pbc,
                                       nullptr, nullptr, nullptr, nullptr, nullptr, nullptr);
    {
        GemmJob a = {p_px, p_pWc, p_pbc, p_pq, p_pkvh, nullptr, 0, NPSG};
        gemm_mma_k<<<dim3(3, GB_PSG_M, 1), 256, SMEM_MMA>>>(a, JZ, JZ, 384, 3, FZ, FZ, FZ);
    }

    // ---- join CSR before first edge pass ----
    cudaStreamWaitEvent(0, evCsr, 0);
    edge_agg_k<<<(NPSG * 32 + 255) / 256, 256>>>(p_pq, p_pkvh, p_roffp, p_colp,
                                                 psg_prel, p_pagg, NPSG);
    {
        GemmJob a = {p_pagg, psg_Wout, psg_bout, p_px, nullptr, p_px, 0, NPSG};
        gemm_mma_k<<<dim3(1, GB_PSG_M, 1), 256, SMEM_MMA>>>(a, JZ, JZ, 128, 2, psg_skip, FZ, FZ);
    }
    colsum2_k<<<dim3((NPSG + 511) / 512, 1), 256>>>(p_px, nullptr, NPSG, p_vec + 128);
    vecadd_k<<<1, 128>>>(p_vec, p_vec + 128, 1.0f / NPSG, p_vec + 256); // fused = qv + psg_ctx

    // ---- two think steps ----
    const float* fused = p_vec + 256;
    for (int i = 0; i < 2; i++) {
        float* tsum = p_vec + 384 + i * 128;   // pre-zeroed in init memset
        build_wc2_k<<<dim3(384, 2), 128>>>(
            ckg_Wkqv + (size_t)(i * 2 + 0) * 128 * 384, ckg_bkqv + (i * 2 + 0) * 384,
            ckg_krel + (size_t)(i * 2 + 0) * 2 * 64 * 64,
            ckg_vrel + (size_t)(i * 2 + 0) * 2 * 64 * 64, p_Wc0, p_bc0,
            ckg_Wkqv + (size_t)(i * 2 + 1) * 128 * 384, ckg_bkqv + (i * 2 + 1) * 384,
            ckg_krel + (size_t)(i * 2 + 1) * 2 * 64 * 64,
            ckg_vrel + (size_t)(i * 2 + 1) * 2 * 64 * 64, p_Wc1, p_bc1);

        {
            GemmJob a = {p_x0, p_Wc0, p_bc0, p_q0, p_kv0h, nullptr, 0, NCKG};
            GemmJob b = {p_x1, p_Wc1, p_bc1, p_q1, p_kv1h, nullptr, 0, NCKG};
            gemm_mma_k<<<dim3(3, GB_CKG_M, 2), 256, SMEM_MMA>>>(a, b, JZ, 384, 3, FZ, fused, FZ);
        }

        edge_agg2_k<<<(2 * NCKG * 32 + 255) / 256, 256>>>(
            p_q1, p_kv0h, p_roff0, p_col0, ckg_prel + i * 4 + 0, p_agg1,
            p_q0, p_kv1h, p_roff1, p_col1, ckg_prel + i * 4 + 2, p_agg0, NCKG);

        float* dst0 = (i == 0) ? p_x0 : out;
        float* dst1 = (i == 0) ? p_x1 : (out + (size_t)NCKG * 128);
        {
            GemmJob a = {p_agg0, ckg_Wout + (size_t)(i * 2 + 0) * 128 * 128,
                         ckg_bout + (i * 2 + 0) * 128, dst0, nullptr, p_x0, i * 2 + 0, NCKG};
            GemmJob b = {p_agg1, ckg_Wout + (size_t)(i * 2 + 1) * 128 * 128,
                         ckg_bout + (i * 2 + 1) * 128, dst1, nullptr, p_x1, i * 2 + 1, NCKG};
            gemm_mma_k<<<dim3(1, GB_CKG_M, 2), 256, SMEM_MMA>>>(a, b, JZ, 128, 2, ckg_skip,
                                                                FZ, fused);
        }

        // fork thought-vector reduction onto s2; step i+1 proceeds on s0 concurrently
        cudaEventRecord(evOutP[i], 0);
        cudaStreamWaitEvent(s2, evOutP[i], 0);
        colsum2_k<<<dim3((NCKG + 511) / 512, 2), 256, 0, s2>>>(dst0, dst1, NCKG, tsum);
        vecscale_k<<<1, 128, 0, s2>>>(tsum, 1.0f / (2 * NCKG),
                                      out + (size_t)2 * NCKG * 128 + i * 128);
        cudaEventRecord(evCsJ[i], s2);
    }

    // ---- join all forked work before capture ends ----
    cudaStreamWaitEvent(0, evCsJ[0], 0);
    cudaStreamWaitEvent(0, evCsJ[1], 0);
}

// round 15
// speedup vs baseline: 1.0782x; 1.0782x over previous
#include <cuda_runtime.h>
#include <cuda_fp16.h>
#include <stdint.h>
#include <math.h>

#define NCKG 50000
#define NPSG 10000
#define ECKG 500000
#define EPSG 100000
#define CH 128

// ---------------- scratch (static device memory; no runtime allocation) ----------------
__device__ float g_x0[NCKG * CH];
__device__ float g_x1[NCKG * CH];
__device__ float g_px[NPSG * CH];
__device__ float g_q0[NCKG * CH];
__device__ float g_q1[NCKG * CH];
__device__ float g_pq[NPSG * CH];
__device__ __half g_kv0h[NCKG * 256];
__device__ __half g_kv1h[NCKG * 256];
__device__ __half g_pkvh[NPSG * 256];
__device__ float g_agg0[NCKG * CH];
__device__ float g_agg1[NCKG * CH];
__device__ float g_pagg[NPSG * CH];
__device__ float g_Wc[4][CH * 384], g_pWc[CH * 384];
__device__ float g_bc[4][384], g_pbc[384];
__device__ int g_deg0[NCKG], g_deg1[NCKG], g_degp[NPSG];
__device__ int g_roff0[NCKG + 1], g_roff1[NCKG + 1], g_roffp[NPSG + 1];
__device__ int g_col0[ECKG], g_col1[ECKG], g_colp[EPSG];
__device__ int g_bs0[64], g_bs1[64], g_bsp[64];
__device__ float g_vec[768]; // [0:128) qv, [128:256) psum, [256:384) fused, [384:512) tsum0, [512:640) tsum1

__device__ __forceinline__ float gelu_exact(float x) {
    return 0.5f * x * (1.0f + erff(x * 0.70710678118654752f));
}
__device__ __forceinline__ uint32_t f2tf32(float x) {
    uint32_t r;
    asm("cvt.rna.tf32.f32 %0, %1;" : "=r"(r) : "f"(x));
    return r;
}
__device__ __forceinline__ void mma_tf32(float* c, const uint32_t* a, const uint32_t* b) {
    asm volatile(
        "mma.sync.aligned.m16n8k8.row.col.f32.tf32.tf32.f32 "
        "{%0,%1,%2,%3}, {%4,%5,%6,%7}, {%8,%9}, {%0,%1,%2,%3};"
        : "+f"(c[0]), "+f"(c[1]), "+f"(c[2]), "+f"(c[3])
        : "r"(a[0]), "r"(a[1]), "r"(a[2]), "r"(a[3]), "r"(b[0]), "r"(b[1]));
}

// padded strides: LDAA % 32 == 4 (A frag loads conflict-free), LDAB % 32 == 8 (B frag loads conflict-free)
#define LDAA 68
#define LDAB 136
#define SMEM_MMA ((128 * LDAA + 64 * LDAB) * 4)   // 69632 B -> 2 blocks/SM (R13-measured best)

struct GemmJob {
    const float* A;       // [M,128]
    const float* W;       // [128,N]
    const float* bias;    // [N]
    float* C;             // fp32 out (mode 1/2: [M,N]; mode 3: q out [M,128])
    __half* Ch;           // mode 3: kv half out [M,256]
    const float* skipx;   // mode 2
    int skipidx;          // mode 2
    int M;
};

// ---------------- tensor-core GEMM: out = epilogue((A+fusedA)[M,128] @ W[128,N] + bias) --
// grid = (N/128, ceil(maxM/128), njobs), block = 256 (8 warps: 4 along M x 2 along N)
// mode 1: relu ; 2: beta*(..)+(1-beta)*(skipx+fusedSkip) ; 3: qkv split (bn==0 -> fp32 q, else half kv)
__global__ __launch_bounds__(256, 2) void gemm_mma_k(
    GemmJob j0, GemmJob j1, GemmJob j2, int N, int mode,
    const float* __restrict__ skipv,
    const float* __restrict__ fusedA, const float* __restrict__ fusedSkip)
{
    const GemmJob& J = (blockIdx.z == 0) ? j0 : (blockIdx.z == 1) ? j1 : j2;
    const int M = J.M;
    const int bm = blockIdx.y * 128;
    if (bm >= M) return;
    const float* __restrict__ A = J.A;
    const float* __restrict__ W = J.W;
    const float* __restrict__ bias = J.bias;

    extern __shared__ uint32_t sm[];
    uint32_t* As = sm;                 // As[row*LDAA + k], k in [0,64)
    uint32_t* Bs = sm + 128 * LDAA;    // Bs[k*LDAB + n]
    const int tid = threadIdx.x;
    const int wid = tid >> 5;
    const int lane = tid & 31;
    const int bn = blockIdx.x * 128;

    const int warp_m = wid & 3;
    const int warp_n = wid >> 2;
    const int g = lane >> 2;
    const int tg = lane & 3;
    const int arow = warp_m * 32 + g;
    const int bcol = warp_n * 64 + g;

    float acc[2][8][4];
#pragma unroll
    for (int t = 0; t < 2; t++)
#pragma unroll
        for (int j = 0; j < 8; j++)
#pragma unroll
            for (int q = 0; q < 4; q++) acc[t][j][q] = 0.f;

#pragma unroll
    for (int s = 0; s < 2; s++) {
        if (s) __syncthreads();
        for (int idx = tid; idx < 128 * 16; idx += 256) {
            int row = idx >> 4;
            int c4 = (idx & 15) * 4;
            int gk = s * 64 + c4;
            float4 v = make_float4(0.f, 0.f, 0.f, 0.f);
            if (bm + row < M) v = *(const float4*)(A + (size_t)(bm + row) * 128 + gk);
            if (fusedA) {
                v.x += fusedA[gk]; v.y += fusedA[gk + 1];
                v.z += fusedA[gk + 2]; v.w += fusedA[gk + 3];
            }
            uint32_t* p = As + row * LDAA + c4;
            p[0] = f2tf32(v.x); p[1] = f2tf32(v.y); p[2] = f2tf32(v.z); p[3] = f2tf32(v.w);
        }
        for (int idx = tid; idx < 64 * 32; idx += 256) {
            int k = idx >> 5;
            int n4 = (idx & 31) * 4;
            float4 v = *(const float4*)(W + (size_t)(s * 64 + k) * N + bn + n4);
            uint32_t* p = Bs + k * LDAB + n4;
            p[0] = f2tf32(v.x); p[1] = f2tf32(v.y); p[2] = f2tf32(v.z); p[3] = f2tf32(v.w);
        }
        __syncthreads();
#pragma unroll
        for (int ks = 0; ks < 8; ks++) {
            const int k0 = ks * 8;
            uint32_t a[2][4];
#pragma unroll
            for (int t = 0; t < 2; t++) {
                int r = arow + t * 16;
                a[t][0] = As[r * LDAA + k0 + tg];
                a[t][1] = As[(r + 8) * LDAA + k0 + tg];
                a[t][2] = As[r * LDAA + k0 + tg + 4];
                a[t][3] = As[(r + 8) * LDAA + k0 + tg + 4];
            }
            uint32_t b[8][2];
#pragma unroll
            for (int j = 0; j < 8; j++) {
                b[j][0] = Bs[(k0 + tg) * LDAB + bcol + j * 8];
                b[j][1] = Bs[(k0 + tg + 4) * LDAB + bcol + j * 8];
            }
#pragma unroll
            for (int t = 0; t < 2; t++)
#pragma unroll
                for (int j = 0; j < 8; j++) mma_tf32(acc[t][j], a[t], b[j]);
        }
    }

    // epilogue
    float beta = 1.f, omb = 0.f;
    if (mode == 2) {
        float sv = skipv[J.skipidx];
        beta = 1.f / (1.f + expf(-sv));
        omb = 1.f - beta;
    }
#pragma unroll
    for (int t = 0; t < 2; t++) {
        int row0 = bm + warp_m * 32 + t * 16 + g;
#pragma unroll
        for (int half = 0; half < 2; half++) {
            int row = row0 + half * 8;
            if (row >= M) continue;
#pragma unroll
            for (int j = 0; j < 8; j++) {
                int col = bn + warp_n * 64 + j * 8 + 2 * tg;
                float v0 = acc[t][j][2 * half + 0] + bias[col];
                float v1 = acc[t][j][2 * half + 1] + bias[col + 1];
                if (mode == 1) {
                    v0 = fmaxf(v0, 0.f); v1 = fmaxf(v1, 0.f);
                    *(float2*)(J.C + (size_t)row * N + col) = make_float2(v0, v1);
                } else if (mode == 2) {
                    float sx0 = J.skipx[(size_t)row * 128 + col];
                    float sx1 = J.skipx[(size_t)row * 128 + col + 1];
                    if (fusedSkip) { sx0 += fusedSkip[col]; sx1 += fusedSkip[col + 1]; }
                    v0 = beta * v0 + omb * sx0;
                    v1 = beta * v1 + omb * sx1;
                    *(float2*)(J.C + (size_t)row * N + col) = make_float2(v0, v1);
                } else { // mode 3: qkv split
                    if (bn == 0) {
                        *(float2*)(J.C + (size_t)row * 128 + col) = make_float2(v0, v1);
                    } else {
                        *(half2*)(J.Ch + (size_t)row * 256 + (col - 128)) =
                            __floats2half2_rn(v0, v1);
                    }
                }
            }
        }
    }
}

// ---------------- combined weight build: Wc = [Wq | Wk@krel | Wv@vrel], bc likewise ----
__device__ __forceinline__ void build_wc_body(
    const float* __restrict__ Wkqv, const float* __restrict__ bkqv,
    const float* __restrict__ krel, const float* __restrict__ vrel,
    float* __restrict__ Wc, float* __restrict__ bc, int j, int r)
{
    float val;
    if (j < 128) {
        val = Wkqv[r * 384 + 128 + j];
        if (r == 0) bc[j] = bkqv[128 + j];
    } else if (j < 256) {
        int h = (j - 128) >> 6, e = (j - 128) & 63;
        const float* kr = krel + h * 4096;
        float s = 0.f;
        for (int d = 0; d < 64; d++) s += Wkqv[r * 384 + h * 64 + d] * kr[d * 64 + e];
        val = s;
        if (r == 0) {
            float bs = 0.f;
            for (int d = 0; d < 64; d++) bs += bkqv[h * 64 + d] * kr[d * 64 + e];
            bc[j] = bs;
        }
    } else {
        int h = (j - 256) >> 6, e = (j - 256) & 63;
        const float* vr = vrel + h * 4096;
        float s = 0.f;
        for (int d = 0; d < 64; d++) s += Wkqv[r * 384 + 256 + h * 64 + d] * vr[d * 64 + e];
        val = s;
        if (r == 0) {
            float bs = 0.f;
            for (int d = 0; d < 64; d++) bs += bkqv[256 + h * 64 + d] * vr[d * 64 + e];
            bc[j] = bs;
        }
    }
    Wc[r * 384 + j] = val;
}

// grid (384, 5): builds PSG set (y=4) + 4 CKG sets (y=0..3) in one launch
__global__ void build_wc_all_k(
    const float* __restrict__ ckg_Wkqv, const float* __restrict__ ckg_bkqv,
    const float* __restrict__ ckg_krel, const float* __restrict__ ckg_vrel,
    float* __restrict__ Wc, float* __restrict__ bc,  // [4][128*384], [4][384]
    const float* __restrict__ psg_Wkqv, const float* __restrict__ psg_bkqv,
    const float* __restrict__ psg_krel, const float* __restrict__ psg_vrel,
    float* __restrict__ pWc, float* __restrict__ pbc)
{
    int y = blockIdx.y;
    if (y < 4) {
        build_wc_body(ckg_Wkqv + (size_t)y * 128 * 384, ckg_bkqv + y * 384,
                      ckg_krel + (size_t)y * 2 * 64 * 64, ckg_vrel + (size_t)y * 2 * 64 * 64,
                      Wc + (size_t)y * 128 * 384, bc + (size_t)y * 384,
                      blockIdx.x, threadIdx.x);
    } else {
        build_wc_body(psg_Wkqv, psg_bkqv, psg_krel, psg_vrel, pWc, pbc,
                      blockIdx.x, threadIdx.x);
    }
}

// ---------------- CSR build (merged launches) ----------------
__global__ void hist3_k(const int* __restrict__ d0, const int* __restrict__ d1,
                        const int* __restrict__ dp,
                        int* __restrict__ deg0, int* __restrict__ deg1, int* __restrict__ degp)
{
    int i = blockIdx.x * blockDim.x + threadIdx.x;
    if (i < ECKG) atomicAdd(&deg0[d0[i]], 1);
    else if (i < 2 * ECKG) atomicAdd(&deg1[d1[i - ECKG]], 1);
    else if (i < 2 * ECKG + EPSG) atomicAdd(&degp[dp[i - 2 * ECKG]], 1);
}

__global__ __launch_bounds__(1024) void scan1_k(
    const int* __restrict__ dg0, int* __restrict__ ex0, int* __restrict__ bs0,
    const int* __restrict__ dg1, int* __restrict__ ex1, int* __restrict__ bs1,
    const int* __restrict__ dgp, int* __restrict__ exp_, int* __restrict__ bsp,
    int nCkg, int nPsg, int nbPsg)
{
    const int* deg; int* ex; int* bsum; int n;
    if (blockIdx.y == 0) { deg = dg0; ex = ex0; bsum = bs0; n = nCkg; }
    else if (blockIdx.y == 1) { deg = dg1; ex = ex1; bsum = bs1; n = nCkg; }
    else { if ((int)blockIdx.x >= nbPsg) return; deg = dgp; ex = exp_; bsum = bsp; n = nPsg; }
    __shared__ int ws[32];
    const int tid = threadIdx.x;
    const int lane = tid & 31, w = tid >> 5;
    const int i = blockIdx.x * 1024 + tid;
    int v = (i < n) ? deg[i] : 0;
    int inc = v;
#pragma unroll
    for (int o = 1; o < 32; o <<= 1) {
        int t = __shfl_up_sync(0xffffffffu, inc, o);
        if (lane >= o) inc += t;
    }
    if (lane == 31) ws[w] = inc;
    __syncthreads();
    if (w == 0) {
        int s = ws[lane];
#pragma unroll
        for (int o = 1; o < 32; o <<= 1) {
            int t = __shfl_up_sync(0xffffffffu, s, o);
            if (lane >= o) s += t;
        }
        ws[lane] = s;
    }
    __syncthreads();
    int exv = ((w == 0) ? 0 : ws[w - 1]) + inc - v;
    if (i < n) ex[i] = exv;
    if (tid == 1023) bsum[blockIdx.x] = exv + v;
}

__global__ void scan2all_k(int* __restrict__ b0, int nb0,
                           int* __restrict__ b1, int nb1,
                           int* __restrict__ b2, int nb2)
{
    if (threadIdx.x != 0) return;
    int* b; int nb;
    if (blockIdx.x == 0) { b = b0; nb = nb0; }
    else if (blockIdx.x == 1) { b = b1; nb = nb1; }
    else { b = b2; nb = nb2; }
    int acc = 0;
    for (int j = 0; j < nb; j++) { int x = b[j]; b[j] = acc; acc += x; }
    b[nb] = acc;
}

__global__ __launch_bounds__(1024) void scan3_k(
    int* __restrict__ ex0, const int* __restrict__ bs0, int* __restrict__ cz0,
    int* __restrict__ ex1, const int* __restrict__ bs1, int* __restrict__ cz1,
    int* __restrict__ exp_, const int* __restrict__ bsp, int* __restrict__ czp,
    int nCkg, int nPsg, int nbCkg, int nbPsg)
{
    int* ex; const int* bsum; int* cz; int n; int nb;
    if (blockIdx.y == 0) { ex = ex0; bsum = bs0; cz = cz0; n = nCkg; nb = nbCkg; }
    else if (blockIdx.y == 1) { ex = ex1; bsum = bs1; cz = cz1; n = nCkg; nb = nbCkg; }
    else { if ((int)blockIdx.x >= nbPsg) return; ex = exp_; bsum = bsp; cz = czp; n = nPsg; nb = nbPsg; }
    int i = blockIdx.x * 1024 + threadIdx.x;
    if (i < n) { ex[i] += bsum[blockIdx.x]; cz[i] = 0; }
    if (i == 0) ex[n] = bsum[nb];
}

__global__ void scatter3_k(
    const int* __restrict__ s0, const int* __restrict__ d0,
    const int* __restrict__ r0, int* __restrict__ c0, int* __restrict__ col0,
    const int* __restrict__ s1, const int* __restrict__ d1,
    const int* __restrict__ r1, int* __restrict__ c1, int* __restrict__ col1,
    const int* __restrict__ sp, const int* __restrict__ dp,
    const int* __restrict__ rp, int* __restrict__ cp, int* __restrict__ colp)
{
    int i = blockIdx.x * blockDim.x + threadIdx.x;
    if (i < ECKG) {
        int d = d0[i];
        col0[r0[d] + atomicAdd(&c0[d], 1)] = s0[i];
    } else if (i < 2 * ECKG) {
        int k = i - ECKG;
        int d = d1[k];
        col1[r1[d] + atomicAdd(&c1[d], 1)] = s1[k];
    } else if (i < 2 * ECKG + EPSG) {
        int k = i - 2 * ECKG;
        int d = dp[k];
        colp[rp[d] + atomicAdd(&cp[d], 1)] = sp[k];
    }
}

// ---------------- edge aggregation (single-pass softmax-weighted sum, warp/dst) --------
__device__ __forceinline__ void edge_node_work(
    const float* __restrict__ qf, const __half* __restrict__ kvh,
    const int* __restrict__ roff, const int* __restrict__ col,
    const float* __restrict__ prel, float* __restrict__ agg, int node, int lane)
{
    const float s0 = prel[0] * 0.125f;
    const float s1 = prel[1] * 0.125f;
    const float2* q2 = (const float2*)(qf + (size_t)node * 128);
    const float2 qa = q2[lane];
    const float2 qb = q2[lane + 32];
    float2 a0 = make_float2(0.f, 0.f), a1 = make_float2(0.f, 0.f);
    float S0 = 0.f, S1 = 0.f;
    const int e0 = roff[node], e1 = roff[node + 1];
    for (int eb = e0; eb < e1; eb += 32) {
        int bat = min(32, e1 - eb);
        int ci = (lane < bat) ? col[eb + lane] : 0;
        int it = 0;
        for (; it + 2 <= bat; it += 2) {
            int sA = __shfl_sync(0xffffffffu, ci, it);
            int sB = __shfl_sync(0xffffffffu, ci, it + 1);
            const half2* kvA = (const half2*)(kvh + (size_t)sA * 256);
            const half2* kvB = (const half2*)(kvh + (size_t)sB * 256);
            float2 k0A = __half22float2(kvA[lane]);
            float2 k1A = __half22float2(kvA[lane + 32]);
            float2 v0A = __half22float2(kvA[lane + 64]);
            float2 v1A = __half22float2(kvA[lane + 96]);
            float2 k0B = __half22float2(kvB[lane]);
            float2 k1B = __half22float2(kvB[lane + 32]);
            float2 v0B = __half22float2(kvB[lane + 64]);
            float2 v1B = __half22float2(kvB[lane + 96]);
            float pA0 = qa.x * k0A.x + qa.y * k0A.y;
            float pA1 = qb.x * k1A.x + qb.y * k1A.y;
            float pB0 = qa.x * k0B.x + qa.y * k0B.y;
            float pB1 = qb.x * k1B.x + qb.y * k1B.y;
#pragma unroll
            for (int o = 16; o; o >>= 1) {
                pA0 += __shfl_xor_sync(0xffffffffu, pA0, o);
                pA1 += __shfl_xor_sync(0xffffffffu, pA1, o);
                pB0 += __shfl_xor_sync(0xffffffffu, pB0, o);
                pB1 += __shfl_xor_sync(0xffffffffu, pB1, o);
            }
            float wA0 = expf(pA0 * s0), wA1 = expf(pA1 * s1);
            float wB0 = expf(pB0 * s0), wB1 = expf(pB1 * s1);
            S0 += wA0 + wB0; S1 += wA1 + wB1;
            a0.x += wA0 * v0A.x + wB0 * v0B.x;
            a0.y += wA0 * v0A.y + wB0 * v0B.y;
            a1.x += wA1 * v1A.x + wB1 * v1B.x;
            a1.y += wA1 * v1A.y + wB1 * v1B.y;
        }
        if (it < bat) {
            int sA = __shfl_sync(0xffffffffu, ci, it);
            const half2* kv = (const half2*)(kvh + (size_t)sA * 256);
            float2 k0 = __half22float2(kv[lane]);
            float2 k1 = __half22float2(kv[lane + 32]);
            float2 v0 = __half22float2(kv[lane + 64]);
            float2 v1 = __half22float2(kv[lane + 96]);
            float p0 = qa.x * k0.x + qa.y * k0.y;
            float p1 = qb.x * k1.x + qb.y * k1.y;
#pragma unroll
            for (int o = 16; o; o >>= 1) {
                p0 += __shfl_xor_sync(0xffffffffu, p0, o);
                p1 += __shfl_xor_sync(0xffffffffu, p1, o);
            }
            float w0 = expf(p0 * s0), w1 = expf(p1 * s1);
            S0 += w0; S1 += w1;
            a0.x += w0 * v0.x; a0.y += w0 * v0.y;
            a1.x += w1 * v1.x; a1.y += w1 * v1.y;
        }
    }
    float i0 = 1.f / (S0 + 1e-16f);
    float i1 = 1.f / (S1 + 1e-16f);
    float2* o = (float2*)(agg + (size_t)node * 128);
    o[lane] = make_float2(gelu_exact(a0.x * i0), gelu_exact(a0.y * i0));
    o[lane + 32] = make_float2(gelu_exact(a1.x * i1), gelu_exact(a1.y * i1));
}

__global__ void edge_agg_k(const float* __restrict__ qf, const __half* __restrict__ kvh,
                           const int* __restrict__ roff, const int* __restrict__ col,
                           const float* __restrict__ prel, float* __restrict__ agg, int Nd)
{
    int warp = (blockIdx.x * blockDim.x + threadIdx.x) >> 5;
    int lane = threadIdx.x & 31;
    if (warp >= Nd) return;
    edge_node_work(qf, kvh, roff, col, prel, agg, warp, lane);
}

__global__ void edge_agg2_k(
    const float* __restrict__ qA, const __half* __restrict__ kvA,
    const int* __restrict__ roffA, const int* __restrict__ colA,
    const float* __restrict__ prelA, float* __restrict__ aggA,
    const float* __restrict__ qB, const __half* __restrict__ kvB,
    const int* __restrict__ roffB, const int* __restrict__ colB,
    const float* __restrict__ prelB, float* __restrict__ aggB, int Nd)
{
    int warp = (blockIdx.x * blockDim.x + threadIdx.x) >> 5;
    int lane = threadIdx.x & 31;
    if (warp < Nd)
        edge_node_work(qA, kvA, roffA, colA, prelA, aggA, warp, lane);
    else if (warp < 2 * Nd)
        edge_node_work(qB, kvB, roffB, colB, prelB, aggB, warp - Nd, lane);
}

// ---------------- small kernels ----------------
__global__ void qv_k(const float* __restrict__ qe, const float* __restrict__ W,
                     const float* __restrict__ b, float* __restrict__ qv)
{
    int c = threadIdx.x;
    float s = 0.f;
    for (int d = 0; d < 768; d++) s += qe[d] * W[d * 128 + c];
    s += b[c];
    qv[c] = fmaxf(s, 0.f);
}

__global__ void colsum2_k(const float* __restrict__ xa, const float* __restrict__ xb,
                          int nrows, float* __restrict__ out)
{
    const float* x = (blockIdx.y == 0) ? xa : xb;
    if (x == nullptr) return;
    int col = threadIdx.x & 127;
    int half = threadIdx.x >> 7;
    long long rbeg = (long long)blockIdx.x * 512 + half;
    long long rend = (long long)(blockIdx.x + 1) * 512;
    if (rend > nrows) rend = nrows;
    float s = 0.f;
    for (long long r = rbeg; r < rend; r += 2) s += x[r * 128 + col];
    atomicAdd(&out[col], s);
}

__global__ void vecadd_k(const float* __restrict__ a, const float* __restrict__ b,
                         float sb, float* __restrict__ o)
{
    int c = threadIdx.x;
    o[c] = a[c] + b[c] * sb;
}

__global__ void vecscale_k(const float* __restrict__ a, float sa, float* __restrict__ o)
{
    int c = threadIdx.x;
    o[c] = a[c] * sa;
}

// ---------------- launch ----------------
extern "C" void kernel_launch(void* const* d_in, const int* in_sizes, int n_in,
                              void* d_out, int out_size)
{
    (void)in_sizes; (void)n_in; (void)out_size;
    const float* ckg_x_dis  = (const float*)d_in[0];
    const float* ckg_x_drug = (const float*)d_in[1];
    const float* psg_x      = (const float*)d_in[2];
    const float* query_emb  = (const float*)d_in[3];
    const float* ckg_lin_W  = (const float*)d_in[4];
    const float* ckg_lin_b  = (const float*)d_in[5];
    const float* psg_lin_W  = (const float*)d_in[6];
    const float* psg_lin_b  = (const float*)d_in[7];
    const float* query_W    = (const float*)d_in[8];
    const float* query_b    = (const float*)d_in[9];
    const float* ckg_Wkqv   = (const float*)d_in[10];
    const float* ckg_bkqv   = (const float*)d_in[11];
    const float* ckg_Wout   = (const float*)d_in[12];
    const float* ckg_bout   = (const float*)d_in[13];
    const float* ckg_skip   = (const float*)d_in[14];
    const float* ckg_krel   = (const float*)d_in[15];
    const float* ckg_vrel   = (const float*)d_in[16];
    const float* ckg_prel   = (const float*)d_in[17];
    const float* psg_Wkqv   = (const float*)d_in[18];
    const float* psg_bkqv   = (const float*)d_in[19];
    const float* psg_Wout   = (const float*)d_in[20];
    const float* psg_bout   = (const float*)d_in[21];
    const float* psg_skip   = (const float*)d_in[22];
    const float* psg_krel   = (const float*)d_in[23];
    const float* psg_vrel   = (const float*)d_in[24];
    const float* psg_prel   = (const float*)d_in[25];
    const int* ei_d2g_src   = (const int*)d_in[26];
    const int* ei_d2g_dst   = (const int*)d_in[27];
    const int* ei_g2d_src   = (const int*)d_in[28];
    const int* ei_g2d_dst   = (const int*)d_in[29];
    const int* psg_src      = (const int*)d_in[30];
    const int* psg_dst      = (const int*)d_in[31];
    float* out = (float*)d_out;

    static int inited = 0;
    static float *p_x0, *p_x1, *p_px, *p_q0, *p_q1, *p_pq;
    static __half *p_kv0h, *p_kv1h, *p_pkvh;
    static float *p_agg0, *p_agg1, *p_pagg;
    static float *p_Wc, *p_pWc, *p_bc, *p_pbc, *p_vec;
    static int *p_deg0, *p_deg1, *p_degp, *p_roff0, *p_roff1, *p_roffp;
    static int *p_col0, *p_col1, *p_colp, *p_bs0, *p_bs1, *p_bsp;
    static cudaStream_t s1, s2;
    static cudaEvent_t evFork, evCsr, evWc, evOutP[2], evCsJ[2];
    if (!inited) {
        cudaGetSymbolAddress((void**)&p_x0, g_x0);
        cudaGetSymbolAddress((void**)&p_x1, g_x1);
        cudaGetSymbolAddress((void**)&p_px, g_px);
        cudaGetSymbolAddress((void**)&p_q0, g_q0);
        cudaGetSymbolAddress((void**)&p_q1, g_q1);
        cudaGetSymbolAddress((void**)&p_pq, g_pq);
        cudaGetSymbolAddress((void**)&p_kv0h, g_kv0h);
        cudaGetSymbolAddress((void**)&p_kv1h, g_kv1h);
        cudaGetSymbolAddress((void**)&p_pkvh, g_pkvh);
        cudaGetSymbolAddress((void**)&p_agg0, g_agg0);
        cudaGetSymbolAddress((void**)&p_agg1, g_agg1);
        cudaGetSymbolAddress((void**)&p_pagg, g_pagg);
        cudaGetSymbolAddress((void**)&p_Wc, g_Wc);
        cudaGetSymbolAddress((void**)&p_pWc, g_pWc);
        cudaGetSymbolAddress((void**)&p_bc, g_bc);
        cudaGetSymbolAddress((void**)&p_pbc, g_pbc);
        cudaGetSymbolAddress((void**)&p_vec, g_vec);
        cudaGetSymbolAddress((void**)&p_deg0, g_deg0);
        cudaGetSymbolAddress((void**)&p_deg1, g_deg1);
        cudaGetSymbolAddress((void**)&p_degp, g_degp);
        cudaGetSymbolAddress((void**)&p_roff0, g_roff0);
        cudaGetSymbolAddress((void**)&p_roff1, g_roff1);
        cudaGetSymbolAddress((void**)&p_roffp, g_roffp);
        cudaGetSymbolAddress((void**)&p_col0, g_col0);
        cudaGetSymbolAddress((void**)&p_col1, g_col1);
        cudaGetSymbolAddress((void**)&p_colp, g_colp);
        cudaGetSymbolAddress((void**)&p_bs0, g_bs0);
        cudaGetSymbolAddress((void**)&p_bs1, g_bs1);
        cudaGetSymbolAddress((void**)&p_bsp, g_bsp);
        cudaFuncSetAttribute(gemm_mma_k, cudaFuncAttributeMaxDynamicSharedMemorySize, SMEM_MMA);
        cudaStreamCreateWithFlags(&s1, cudaStreamNonBlocking);
        cudaStreamCreateWithFlags(&s2, cudaStreamNonBlocking);
        cudaEventCreateWithFlags(&evFork, cudaEventDisableTiming);
        cudaEventCreateWithFlags(&evCsr, cudaEventDisableTiming);
        cudaEventCreateWithFlags(&evWc, cudaEventDisableTiming);
        for (int i = 0; i < 2; i++) {
            cudaEventCreateWithFlags(&evOutP[i], cudaEventDisableTiming);
            cudaEventCreateWithFlags(&evCsJ[i], cudaEventDisableTiming);
        }
        inited = 1;
    }

    const int GB_CKG_M = (NCKG + 127) / 128;  // 391
    const int GB_PSG_M = (NPSG + 127) / 128;  // 79
    const int NB_CKG = (NCKG + 1023) / 1024;  // 49
    const int NB_PSG = (NPSG + 1023) / 1024;  // 10
    const int ETOT = 2 * ECKG + EPSG;         // 1.1M
    const float* FZ = nullptr;
    GemmJob JZ = {};

    // ---- fork: CSR chain on s1, weight builds on s2 ----
    cudaEventRecord(evFork, 0);
    cudaStreamWaitEvent(s1, evFork, 0);
    cudaStreamWaitEvent(s2, evFork, 0);

    // ---- s1: full CSR build chain ----
    cudaMemsetAsync(p_deg0, 0, NCKG * sizeof(int), s1);
    cudaMemsetAsync(p_deg1, 0, NCKG * sizeof(int), s1);
    cudaMemsetAsync(p_degp, 0, NPSG * sizeof(int), s1);
    hist3_k<<<(ETOT + 255) / 256, 256, 0, s1>>>(ei_d2g_dst, ei_g2d_dst, psg_dst,
                                                p_deg0, p_deg1, p_degp);
    scan1_k<<<dim3(NB_CKG, 3), 1024, 0, s1>>>(p_deg0, p_roff0, p_bs0, p_deg1, p_roff1, p_bs1,
                                              p_degp, p_roffp, p_bsp, NCKG, NPSG, NB_PSG);
    scan2all_k<<<3, 32, 0, s1>>>(p_bs0, NB_CKG, p_bs1, NB_CKG, p_bsp, NB_PSG);
    scan3_k<<<dim3(NB_CKG, 3), 1024, 0, s1>>>(p_roff0, p_bs0, p_deg0, p_roff1, p_bs1, p_deg1,
                                              p_roffp, p_bsp, p_degp, NCKG, NPSG, NB_CKG, NB_PSG);
    scatter3_k<<<(ETOT + 255) / 256, 256, 0, s1>>>(
        ei_d2g_src, ei_d2g_dst, p_roff0, p_deg0, p_col0,
        ei_g2d_src, ei_g2d_dst, p_roff1, p_deg1, p_col1,
        psg_src, psg_dst, p_roffp, p_degp, p_colp);
    cudaEventRecord(evCsr, s1);

    // ---- s2: all 5 combined-weight builds (PSG + 4 CKG) ----
    build_wc_all_k<<<dim3(384, 5), 128, 0, s2>>>(
        ckg_Wkqv, ckg_bkqv, ckg_krel, ckg_vrel, p_Wc, p_bc,
        psg_Wkqv, psg_bkqv, psg_krel, psg_vrel, p_pWc, p_pbc);
    cudaEventRecord(evWc, s2);

    // ---- s0 (capture stream): projections, concurrent with CSR + wc builds ----
    cudaMemsetAsync(p_vec, 0, 768 * sizeof(float));
    qv_k<<<1, 128>>>(query_emb, query_W, query_b, p_vec);
    {
        GemmJob a = {ckg_x_dis, ckg_lin_W, ckg_lin_b, p_x0, nullptr, nullptr, 0, NCKG};
        GemmJob b = {ckg_x_drug, ckg_lin_W + 128 * 128, ckg_lin_b + 128, p_x1, nullptr, nullptr, 0, NCKG};
        GemmJob c = {psg_x, psg_lin_W, psg_lin_b, p_px, nullptr, nullptr, 0, NPSG};
        gemm_mma_k<<<dim3(1, GB_CKG_M, 3), 256, SMEM_MMA>>>(a, b, c, 128, 1, FZ, FZ, FZ);
    }

    // ---- join wc builds before PSG qkv GEMM ----
    cudaStreamWaitEvent(0, evWc, 0);
    {
        GemmJob a = {p_px, p_pWc, p_pbc, p_pq, p_pkvh, nullptr, 0, NPSG};
        gemm_mma_k<<<dim3(3, GB_PSG_M, 1), 256, SMEM_MMA>>>(a, JZ, JZ, 384, 3, FZ, FZ, FZ);
    }

    // ---- join CSR before first edge pass ----
    cudaStreamWaitEvent(0, evCsr, 0);
    edge_agg_k<<<(NPSG * 32 + 255) / 256, 256>>>(p_pq, p_pkvh, p_roffp, p_colp,
                                                 psg_prel, p_pagg, NPSG);
    {
        GemmJob a = {p_pagg, psg_Wout, psg_bout, p_px, nullptr, p_px, 0, NPSG};
        gemm_mma_k<<<dim3(1, GB_PSG_M, 1), 256, SMEM_MMA>>>(a, JZ, JZ, 128, 2, psg_skip, FZ, FZ);
    }
    colsum2_k<<<dim3((NPSG + 511) / 512, 1), 256>>>(p_px, nullptr, NPSG, p_vec + 128);
    vecadd_k<<<1, 128>>>(p_vec, p_vec + 128, 1.0f / NPSG, p_vec + 256); // fused = qv + psg_ctx

    // ---- two think steps (Wc pre-built) ----
    const float* fused = p_vec + 256;
    for (int i = 0; i < 2; i++) {
        float* tsum = p_vec + 384 + i * 128;   // pre-zeroed in init memset
        const float* Wc0 = p_Wc + (size_t)(i * 2 + 0) * 128 * 384;
        const float* Wc1 = p_Wc + (size_t)(i * 2 + 1) * 128 * 384;
        const float* bc0 = p_bc + (size_t)(i * 2 + 0) * 384;
        const float* bc1 = p_bc + (size_t)(i * 2 + 1) * 384;

        {
            GemmJob a = {p_x0, Wc0, bc0, p_q0, p_kv0h, nullptr, 0, NCKG};
            GemmJob b = {p_x1, Wc1, bc1, p_q1, p_kv1h, nullptr, 0, NCKG};
            gemm_mma_k<<<dim3(3, GB_CKG_M, 2), 256, SMEM_MMA>>>(a, b, JZ, 384, 3, FZ, fused, FZ);
        }

        edge_agg2_k<<<(2 * NCKG * 32 + 255) / 256, 256>>>(
            p_q1, p_kv0h, p_roff0, p_col0, ckg_prel + i * 4 + 0, p_agg1,
            p_q0, p_kv1h, p_roff1, p_col1, ckg_prel + i * 4 + 2, p_agg0, NCKG);

        float* dst0 = (i == 0) ? p_x0 : out;
        float* dst1 = (i == 0) ? p_x1 : (out + (size_t)NCKG * 128);
        {
            GemmJob a = {p_agg0, ckg_Wout + (size_t)(i * 2 + 0) * 128 * 128,
                         ckg_bout + (i * 2 + 0) * 128, dst0, nullptr, p_x0, i * 2 + 0, NCKG};
            GemmJob b = {p_agg1, ckg_Wout + (size_t)(i * 2 + 1) * 128 * 128,
                         ckg_bout + (i * 2 + 1) * 128, dst1, nullptr, p_x1, i * 2 + 1, NCKG};
            gemm_mma_k<<<dim3(1, GB_CKG_M, 2), 256, SMEM_MMA>>>(a, b, JZ, 128, 2, ckg_skip,
                                                                FZ, fused);
        }

        // fork thought-vector reduction onto s2; step i+1 proceeds on s0 concurrently
        cudaEventRecord(evOutP[i], 0);
        cudaStreamWaitEvent(s2, evOutP[i], 0);
        colsum2_k<<<dim3((NCKG + 511) / 512, 2), 256, 0, s2>>>(dst0, dst1, NCKG, tsum);
        vecscale_k<<<1, 128, 0, s2>>>(tsum, 1.0f / (2 * NCKG),
                                      out + (size_t)2 * NCKG * 128 + i * 128);
        cudaEventRecord(evCsJ[i], s2);
    }

    // ---- join all forked work before capture ends ----
    cudaStreamWaitEvent(0, evCsJ[0], 0);
    cudaStreamWaitEvent(0, evCsJ[1], 0);
}

// round 16
// speedup vs baseline: 1.1099x; 1.0294x over previous
#include <cuda_runtime.h>
#include <cuda_fp16.h>
#include <stdint.h>
#include <math.h>

#define NCKG 50000
#define NPSG 10000
#define ECKG 500000
#define EPSG 100000
#define CH 128

// ---------------- scratch (static device memory; no runtime allocation) ----------------
__device__ float g_x0[NCKG * CH];
__device__ float g_x1[NCKG * CH];
__device__ float g_px[NPSG * CH];
__device__ float g_q0[NCKG * CH];
__device__ float g_q1[NCKG * CH];
__device__ float g_pq[NPSG * CH];
__device__ __half g_kv0h[NCKG * 256];
__device__ __half g_kv1h[NCKG * 256];
__device__ __half g_pkvh[NPSG * 256];
__device__ float g_agg0[NCKG * CH];
__device__ float g_agg1[NCKG * CH];
__device__ float g_pagg[NPSG * CH];
__device__ float g_Wc[4][CH * 384], g_pWc[CH * 384];
__device__ float g_bc[4][384], g_pbc[384];
__device__ int g_deg0[NCKG], g_deg1[NCKG], g_degp[NPSG];
__device__ int g_roff0[NCKG + 1], g_roff1[NCKG + 1], g_roffp[NPSG + 1];
__device__ int g_col0[ECKG], g_col1[ECKG], g_colp[EPSG];
__device__ int g_bs0[64], g_bs1[64], g_bsp[64];
__device__ float g_vec[768]; // [0:128) qv, [128:256) psum, [256:384) fused, [384:512) tsum0, [512:640) tsum1

__device__ __forceinline__ float gelu_exact(float x) {
    return 0.5f * x * (1.0f + erff(x * 0.70710678118654752f));
}
__device__ __forceinline__ void mma_f16(float* c, const uint32_t* a, const uint32_t* b) {
    asm volatile(
        "mma.sync.aligned.m16n8k16.row.col.f32.f16.f16.f32 "
        "{%0,%1,%2,%3}, {%4,%5,%6,%7}, {%8,%9}, {%0,%1,%2,%3};"
        : "+f"(c[0]), "+f"(c[1]), "+f"(c[2]), "+f"(c[3])
        : "r"(a[0]), "r"(a[1]), "r"(a[2]), "r"(a[3]), "r"(b[0]), "r"(b[1]));
}
__device__ __forceinline__ uint32_t pack_h2(float lo, float hi) {
    __half2 h = __floats2half2_rn(lo, hi);
    return *(uint32_t*)&h;
}

// LDH (uint32/half2 stride) == 36: 36 % 32 == 4 -> fragment-load banks (4g + tg) all
// distinct over g in [0,8) x tg in [0,4): conflict-free mainloop loads for A and B.
#define LDH 36
#define SMEM_MMA (2 * 128 * LDH * 4)   // 36864 B

struct GemmJob {
    const float* A;       // [M,128]
    const float* W;       // [128,N]
    const float* bias;    // [N]
    float* C;             // fp32 out (mode 1/2: [M,N]; mode 3: q out [M,128])
    __half* Ch;           // mode 3: kv half out [M,256]
    const float* skipx;   // mode 2
    int skipidx;          // mode 2
    int M;
};

// ---------------- tensor-core GEMM (fp16 m16n8k16): out = epi((A+fusedA) @ W + bias) ----
// grid = (N/128, ceil(maxM/128), njobs), block = 256 (8 warps: 4 along M x 2 along N)
// mode 1: relu ; 2: beta*(..)+(1-beta)*(skipx+fusedSkip) ; 3: qkv split (bn==0 -> fp32 q, else half kv)
__global__ __launch_bounds__(256, 2) void gemm_mma_k(
    GemmJob j0, GemmJob j1, GemmJob j2, int N, int mode,
    const float* __restrict__ skipv,
    const float* __restrict__ fusedA, const float* __restrict__ fusedSkip)
{
    const GemmJob& J = (blockIdx.z == 0) ? j0 : (blockIdx.z == 1) ? j1 : j2;
    const int M = J.M;
    const int bm = blockIdx.y * 128;
    if (bm >= M) return;
    const float* __restrict__ A = J.A;
    const float* __restrict__ W = J.W;
    const float* __restrict__ bias = J.bias;

    extern __shared__ uint32_t sm[];
    uint32_t* As = sm;                 // half2 [row][LDH], 64 k-halves (32 words) per stage
    uint32_t* Bs = sm + 128 * LDH;     // half2 [n][LDH], transposed, 64 k-halves per stage
    const int tid = threadIdx.x;
    const int wid = tid >> 5;
    const int lane = tid & 31;
    const int bn = blockIdx.x * 128;

    const int warp_m = wid & 3;
    const int warp_n = wid >> 2;
    const int g = lane >> 2;
    const int tg = lane & 3;
    const int arow = warp_m * 32 + g;
    const int bcol = warp_n * 64 + g;

    float acc[2][8][4];
#pragma unroll
    for (int t = 0; t < 2; t++)
#pragma unroll
        for (int j = 0; j < 8; j++)
#pragma unroll
            for (int q = 0; q < 4; q++) acc[t][j][q] = 0.f;

#pragma unroll
    for (int s = 0; s < 2; s++) {
        if (s) __syncthreads();
        // stage A half-K: 128 rows x 64 k (fp32 -> half2)
        for (int idx = tid; idx < 128 * 16; idx += 256) {
            int row = idx >> 4;
            int c4 = (idx & 15) * 4;
            int gk = s * 64 + c4;
            float4 v = make_float4(0.f, 0.f, 0.f, 0.f);
            if (bm + row < M) v = *(const float4*)(A + (size_t)(bm + row) * 128 + gk);
            if (fusedA) {
                v.x += fusedA[gk]; v.y += fusedA[gk + 1];
                v.z += fusedA[gk + 2]; v.w += fusedA[gk + 3];
            }
            As[row * LDH + c4 / 2] = pack_h2(v.x, v.y);
            As[row * LDH + c4 / 2 + 1] = pack_h2(v.z, v.w);
        }
        // stage B half-K transposed: Bs[n][k], packing (k, k+1) into one half2
        for (int u = tid; u < 128 * 32; u += 256) {
            int n = u & 127;      // 32 consecutive lanes -> consecutive n: coalesced W reads
            int kp = u >> 7;      // half2 word 0..31
            int gk = s * 64 + kp * 2;
            float w0 = W[(size_t)gk * N + bn + n];
            float w1 = W[(size_t)(gk + 1) * N + bn + n];
            Bs[n * LDH + kp] = pack_h2(w0, w1);
        }
        __syncthreads();
#pragma unroll
        for (int ks = 0; ks < 4; ks++) {     // 4 k-steps of 16 per 64-k stage
            const int k0w = ks * 8;          // half2-word base
            uint32_t a[2][4];
#pragma unroll
            for (int t = 0; t < 2; t++) {
                int r = arow + t * 16;
                a[t][0] = As[r * LDH + k0w + tg];
                a[t][1] = As[(r + 8) * LDH + k0w + tg];
                a[t][2] = As[r * LDH + k0w + 4 + tg];
                a[t][3] = As[(r + 8) * LDH + k0w + 4 + tg];
            }
            uint32_t b[8][2];
#pragma unroll
            for (int j = 0; j < 8; j++) {
                int row = bcol + j * 8;
                b[j][0] = Bs[row * LDH + k0w + tg];
                b[j][1] = Bs[row * LDH + k0w + 4 + tg];
            }
#pragma unroll
            for (int t = 0; t < 2; t++)
#pragma unroll
                for (int j = 0; j < 8; j++) mma_f16(acc[t][j], a[t], b[j]);
        }
    }

    // epilogue
    float beta = 1.f, omb = 0.f;
    if (mode == 2) {
        float sv = skipv[J.skipidx];
        beta = 1.f / (1.f + expf(-sv));
        omb = 1.f - beta;
    }
#pragma unroll
    for (int t = 0; t < 2; t++) {
        int row0 = bm + warp_m * 32 + t * 16 + g;
#pragma unroll
        for (int half = 0; half < 2; half++) {
            int row = row0 + half * 8;
            if (row >= M) continue;
#pragma unroll
            for (int j = 0; j < 8; j++) {
                int col = bn + warp_n * 64 + j * 8 + 2 * tg;
                float v0 = acc[t][j][2 * half + 0] + bias[col];
                float v1 = acc[t][j][2 * half + 1] + bias[col + 1];
                if (mode == 1) {
                    v0 = fmaxf(v0, 0.f); v1 = fmaxf(v1, 0.f);
                    *(float2*)(J.C + (size_t)row * N + col) = make_float2(v0, v1);
                } else if (mode == 2) {
                    float sx0 = J.skipx[(size_t)row * 128 + col];
                    float sx1 = J.skipx[(size_t)row * 128 + col + 1];
                    if (fusedSkip) { sx0 += fusedSkip[col]; sx1 += fusedSkip[col + 1]; }
                    v0 = beta * v0 + omb * sx0;
                    v1 = beta * v1 + omb * sx1;
                    *(float2*)(J.C + (size_t)row * N + col) = make_float2(v0, v1);
                } else { // mode 3: qkv split
                    if (bn == 0) {
                        *(float2*)(J.C + (size_t)row * 128 + col) = make_float2(v0, v1);
                    } else {
                        *(half2*)(J.Ch + (size_t)row * 256 + (col - 128)) =
                            __floats2half2_rn(v0, v1);
                    }
                }
            }
        }
    }
}

// ---------------- combined weight build: Wc = [Wq | Wk@krel | Wv@vrel], bc likewise ----
__device__ __forceinline__ void build_wc_body(
    const float* __restrict__ Wkqv, const float* __restrict__ bkqv,
    const float* __restrict__ krel, const float* __restrict__ vrel,
    float* __restrict__ Wc, float* __restrict__ bc, int j, int r)
{
    float val;
    if (j < 128) {
        val = Wkqv[r * 384 + 128 + j];
        if (r == 0) bc[j] = bkqv[128 + j];
    } else if (j < 256) {
        int h = (j - 128) >> 6, e = (j - 128) & 63;
        const float* kr = krel + h * 4096;
        float s = 0.f;
        for (int d = 0; d < 64; d++) s += Wkqv[r * 384 + h * 64 + d] * kr[d * 64 + e];
        val = s;
        if (r == 0) {
            float bs = 0.f;
            for (int d = 0; d < 64; d++) bs += bkqv[h * 64 + d] * kr[d * 64 + e];
            bc[j] = bs;
        }
    } else {
        int h = (j - 256) >> 6, e = (j - 256) & 63;
        const float* vr = vrel + h * 4096;
        float s = 0.f;
        for (int d = 0; d < 64; d++) s += Wkqv[r * 384 + 256 + h * 64 + d] * vr[d * 64 + e];
        val = s;
        if (r == 0) {
            float bs = 0.f;
            for (int d = 0; d < 64; d++) bs += bkqv[256 + h * 64 + d] * vr[d * 64 + e];
            bc[j] = bs;
        }
    }
    Wc[r * 384 + j] = val;
}

// grid (384, 5): builds PSG set (y=4) + 4 CKG sets (y=0..3) in one launch
__global__ void build_wc_all_k(
    const float* __restrict__ ckg_Wkqv, const float* __restrict__ ckg_bkqv,
    const float* __restrict__ ckg_krel, const float* __restrict__ ckg_vrel,
    float* __restrict__ Wc, float* __restrict__ bc,
    const float* __restrict__ psg_Wkqv, const float* __restrict__ psg_bkqv,
    const float* __restrict__ psg_krel, const float* __restrict__ psg_vrel,
    float* __restrict__ pWc, float* __restrict__ pbc)
{
    int y = blockIdx.y;
    if (y < 4) {
        build_wc_body(ckg_Wkqv + (size_t)y * 128 * 384, ckg_bkqv + y * 384,
                      ckg_krel + (size_t)y * 2 * 64 * 64, ckg_vrel + (size_t)y * 2 * 64 * 64,
                      Wc + (size_t)y * 128 * 384, bc + (size_t)y * 384,
                      blockIdx.x, threadIdx.x);
    } else {
        build_wc_body(psg_Wkqv, psg_bkqv, psg_krel, psg_vrel, pWc, pbc,
                      blockIdx.x, threadIdx.x);
    }
}

// ---------------- CSR build (merged launches) ----------------
__global__ void hist3_k(const int* __restrict__ d0, const int* __restrict__ d1,
                        const int* __restrict__ dp,
                        int* __restrict__ deg0, int* __restrict__ deg1, int* __restrict__ degp)
{
    int i = blockIdx.x * blockDim.x + threadIdx.x;
    if (i < ECKG) atomicAdd(&deg0[d0[i]], 1);
    else if (i < 2 * ECKG) atomicAdd(&deg1[d1[i - ECKG]], 1);
    else if (i < 2 * ECKG + EPSG) atomicAdd(&degp[dp[i - 2 * ECKG]], 1);
}

__global__ __launch_bounds__(1024) void scan1_k(
    const int* __restrict__ dg0, int* __restrict__ ex0, int* __restrict__ bs0,
    const int* __restrict__ dg1, int* __restrict__ ex1, int* __restrict__ bs1,
    const int* __restrict__ dgp, int* __restrict__ exp_, int* __restrict__ bsp,
    int nCkg, int nPsg, int nbPsg)
{
    const int* deg; int* ex; int* bsum; int n;
    if (blockIdx.y == 0) { deg = dg0; ex = ex0; bsum = bs0; n = nCkg; }
    else if (blockIdx.y == 1) { deg = dg1; ex = ex1; bsum = bs1; n = nCkg; }
    else { if ((int)blockIdx.x >= nbPsg) return; deg = dgp; ex = exp_; bsum = bsp; n = nPsg; }
    __shared__ int ws[32];
    const int tid = threadIdx.x;
    const int lane = tid & 31, w = tid >> 5;
    const int i = blockIdx.x * 1024 + tid;
    int v = (i < n) ? deg[i] : 0;
    int inc = v;
#pragma unroll
    for (int o = 1; o < 32; o <<= 1) {
        int t = __shfl_up_sync(0xffffffffu, inc, o);
        if (lane >= o) inc += t;
    }
    if (lane == 31) ws[w] = inc;
    __syncthreads();
    if (w == 0) {
        int s = ws[lane];
#pragma unroll
        for (int o = 1; o < 32; o <<= 1) {
            int t = __shfl_up_sync(0xffffffffu, s, o);
            if (lane >= o) s += t;
        }
        ws[lane] = s;
    }
    __syncthreads();
    int exv = ((w == 0) ? 0 : ws[w - 1]) + inc - v;
    if (i < n) ex[i] = exv;
    if (tid == 1023) bsum[blockIdx.x] = exv + v;
}

__global__ void scan2all_k(int* __restrict__ b0, int nb0,
                           int* __restrict__ b1, int nb1,
                           int* __restrict__ b2, int nb2)
{
    if (threadIdx.x != 0) return;
    int* b; int nb;
    if (blockIdx.x == 0) { b = b0; nb = nb0; }
    else if (blockIdx.x == 1) { b = b1; nb = nb1; }
    else { b = b2; nb = nb2; }
    int acc = 0;
    for (int j = 0; j < nb; j++) { int x = b[j]; b[j] = acc; acc += x; }
    b[nb] = acc;
}

__global__ __launch_bounds__(1024) void scan3_k(
    int* __restrict__ ex0, const int* __restrict__ bs0, int* __restrict__ cz0,
    int* __restrict__ ex1, const int* __restrict__ bs1, int* __restrict__ cz1,
    int* __restrict__ exp_, const int* __restrict__ bsp, int* __restrict__ czp,
    int nCkg, int nPsg, int nbCkg, int nbPsg)
{
    int* ex; const int* bsum; int* cz; int n; int nb;
    if (blockIdx.y == 0) { ex = ex0; bsum = bs0; cz = cz0; n = nCkg; nb = nbCkg; }
    else if (blockIdx.y == 1) { ex = ex1; bsum = bs1; cz = cz1; n = nCkg; nb = nbCkg; }
    else { if ((int)blockIdx.x >= nbPsg) return; ex = exp_; bsum = bsp; cz = czp; n = nPsg; nb = nbPsg; }
    int i = blockIdx.x * 1024 + threadIdx.x;
    if (i < n) { ex[i] += bsum[blockIdx.x]; cz[i] = 0; }
    if (i == 0) ex[n] = bsum[nb];
}

__global__ void scatter3_k(
    const int* __restrict__ s0, const int* __restrict__ d0,
    const int* __restrict__ r0, int* __restrict__ c0, int* __restrict__ col0,
    const int* __restrict__ s1, const int* __restrict__ d1,
    const int* __restrict__ r1, int* __restrict__ c1, int* __restrict__ col1,
    const int* __restrict__ sp, const int* __restrict__ dp,
    const int* __restrict__ rp, int* __restrict__ cp, int* __restrict__ colp)
{
    int i = blockIdx.x * blockDim.x + threadIdx.x;
    if (i < ECKG) {
        int d = d0[i];
        col0[r0[d] + atomicAdd(&c0[d], 1)] = s0[i];
    } else if (i < 2 * ECKG) {
        int k = i - ECKG;
        int d = d1[k];
        col1[r1[d] + atomicAdd(&c1[d], 1)] = s1[k];
    } else if (i < 2 * ECKG + EPSG) {
        int k = i - 2 * ECKG;
        int d = dp[k];
        colp[rp[d] + atomicAdd(&cp[d], 1)] = sp[k];
    }
}

// ---------------- edge aggregation (single-pass softmax-weighted sum, warp/dst) --------
__device__ __forceinline__ void edge_node_work(
    const float* __restrict__ qf, const __half* __restrict__ kvh,
    const int* __restrict__ roff, const int* __restrict__ col,
    const float* __restrict__ prel, float* __restrict__ agg, int node, int lane)
{
    const float s0 = prel[0] * 0.125f;
    const float s1 = prel[1] * 0.125f;
    const float2* q2 = (const float2*)(qf + (size_t)node * 128);
    const float2 qa = q2[lane];
    const float2 qb = q2[lane + 32];
    float2 a0 = make_float2(0.f, 0.f), a1 = make_float2(0.f, 0.f);
    float S0 = 0.f, S1 = 0.f;
    const int e0 = roff[node], e1 = roff[node + 1];
    for (int eb = e0; eb < e1; eb += 32) {
        int bat = min(32, e1 - eb);
        int ci = (lane < bat) ? col[eb + lane] : 0;
        int it = 0;
        for (; it + 2 <= bat; it += 2) {
            int sA = __shfl_sync(0xffffffffu, ci, it);
            int sB = __shfl_sync(0xffffffffu, ci, it + 1);
            const half2* kvA = (const half2*)(kvh + (size_t)sA * 256);
            const half2* kvB = (const half2*)(kvh + (size_t)sB * 256);
            float2 k0A = __half22float2(kvA[lane]);
            float2 k1A = __half22float2(kvA[lane + 32]);
            float2 v0A = __half22float2(kvA[lane + 64]);
            float2 v1A = __half22float2(kvA[lane + 96]);
            float2 k0B = __half22float2(kvB[lane]);
            float2 k1B = __half22float2(kvB[lane + 32]);
            float2 v0B = __half22float2(kvB[lane + 64]);
            float2 v1B = __half22float2(kvB[lane + 96]);
            float pA0 = qa.x * k0A.x + qa.y * k0A.y;
            float pA1 = qb.x * k1A.x + qb.y * k1A.y;
            float pB0 = qa.x * k0B.x + qa.y * k0B.y;
            float pB1 = qb.x * k1B.x + qb.y * k1B.y;
#pragma unroll
            for (int o = 16; o; o >>= 1) {
                pA0 += __shfl_xor_sync(0xffffffffu, pA0, o);
                pA1 += __shfl_xor_sync(0xffffffffu, pA1, o);
                pB0 += __shfl_xor_sync(0xffffffffu, pB0, o);
                pB1 += __shfl_xor_sync(0xffffffffu, pB1, o);
            }
            float wA0 = expf(pA0 * s0), wA1 = expf(pA1 * s1);
            float wB0 = expf(pB0 * s0), wB1 = expf(pB1 * s1);
            S0 += wA0 + wB0; S1 += wA1 + wB1;
            a0.x += wA0 * v0A.x + wB0 * v0B.x;
            a0.y += wA0 * v0A.y + wB0 * v0B.y;
            a1.x += wA1 * v1A.x + wB1 * v1B.x;
            a1.y += wA1 * v1A.y + wB1 * v1B.y;
        }
        if (it < bat) {
            int sA = __shfl_sync(0xffffffffu, ci, it);
            const half2* kv = (const half2*)(kvh + (size_t)sA * 256);
            float2 k0 = __half22float2(kv[lane]);
            float2 k1 = __half22float2(kv[lane + 32]);
            float2 v0 = __half22float2(kv[lane + 64]);
            float2 v1 = __half22float2(kv[lane + 96]);
            float p0 = qa.x * k0.x + qa.y * k0.y;
            float p1 = qb.x * k1.x + qb.y * k1.y;
#pragma unroll
            for (int o = 16; o; o >>= 1) {
                p0 += __shfl_xor_sync(0xffffffffu, p0, o);
                p1 += __shfl_xor_sync(0xffffffffu, p1, o);
            }
            float w0 = expf(p0 * s0), w1 = expf(p1 * s1);
            S0 += w0; S1 += w1;
            a0.x += w0 * v0.x; a0.y += w0 * v0.y;
            a1.x += w1 * v1.x; a1.y += w1 * v1.y;
        }
    }
    float i0 = 1.f / (S0 + 1e-16f);
    float i1 = 1.f / (S1 + 1e-16f);
    float2* o = (float2*)(agg + (size_t)node * 128);
    o[lane] = make_float2(gelu_exact(a0.x * i0), gelu_exact(a0.y * i0));
    o[lane + 32] = make_float2(gelu_exact(a1.x * i1), gelu_exact(a1.y * i1));
}

__global__ void edge_agg_k(const float* __restrict__ qf, const __half* __restrict__ kvh,
                           const int* __restrict__ roff, const int* __restrict__ col,
                           const float* __restrict__ prel, float* __restrict__ agg, int Nd)
{
    int warp = (blockIdx.x * blockDim.x + threadIdx.x) >> 5;
    int lane = threadIdx.x & 31;
    if (warp >= Nd) return;
    edge_node_work(qf, kvh, roff, col, prel, agg, warp, lane);
}

__global__ void edge_agg2_k(
    const float* __restrict__ qA, const __half* __restrict__ kvA,
    const int* __restrict__ roffA, const int* __restrict__ colA,
    const float* __restrict__ prelA, float* __restrict__ aggA,
    const float* __restrict__ qB, const __half* __restrict__ kvB,
    const int* __restrict__ roffB, const int* __restrict__ colB,
    const float* __restrict__ prelB, float* __restrict__ aggB, int Nd)
{
    int warp = (blockIdx.x * blockDim.x + threadIdx.x) >> 5;
    int lane = threadIdx.x & 31;
    if (warp < Nd)
        edge_node_work(qA, kvA, roffA, colA, prelA, aggA, warp, lane);
    else if (warp < 2 * Nd)
        edge_node_work(qB, kvB, roffB, colB, prelB, aggB, warp - Nd, lane);
}

// ---------------- small kernels ----------------
__global__ void qv_k(const float* __restrict__ qe, const float* __restrict__ W,
                     const float* __restrict__ b, float* __restrict__ qv)
{
    int c = threadIdx.x;
    float s = 0.f;
    for (int d = 0; d < 768; d++) s += qe[d] * W[d * 128 + c];
    s += b[c];
    qv[c] = fmaxf(s, 0.f);
}

__global__ void colsum2_k(const float* __restrict__ xa, const float* __restrict__ xb,
                          int nrows, float* __restrict__ out)
{
    const float* x = (blockIdx.y == 0) ? xa : xb;
    if (x == nullptr) return;
    int col = threadIdx.x & 127;
    int half = threadIdx.x >> 7;
    long long rbeg = (long long)blockIdx.x * 512 + half;
    long long rend = (long long)(blockIdx.x + 1) * 512;
    if (rend > nrows) rend = nrows;
    float s = 0.f;
    for (long long r = rbeg; r < rend; r += 2) s += x[r * 128 + col];
    atomicAdd(&out[col], s);
}

__global__ void vecadd_k(const float* __restrict__ a, const float* __restrict__ b,
                         float sb, float* __restrict__ o)
{
    int c = threadIdx.x;
    o[c] = a[c] + b[c] * sb;
}

__global__ void vecscale_k(const float* __restrict__ a, float sa, float* __restrict__ o)
{
    int c = threadIdx.x;
    o[c] = a[c] * sa;
}

// ---------------- launch ----------------
extern "C" void kernel_launch(void* const* d_in, const int* in_sizes, int n_in,
                              void* d_out, int out_size)
{
    (void)in_sizes; (void)n_in; (void)out_size;
    const float* ckg_x_dis  = (const float*)d_in[0];
    const float* ckg_x_drug = (const float*)d_in[1];
    const float* psg_x      = (const float*)d_in[2];
    const float* query_emb  = (const float*)d_in[3];
    const float* ckg_lin_W  = (const float*)d_in[4];
    const float* ckg_lin_b  = (const float*)d_in[5];
    const float* psg_lin_W  = (const float*)d_in[6];
    const float* psg_lin_b  = (const float*)d_in[7];
    const float* query_W    = (const float*)d_in[8];
    const float* query_b    = (const float*)d_in[9];
    const float* ckg_Wkqv   = (const float*)d_in[10];
    const float* ckg_bkqv   = (const float*)d_in[11];
    const float* ckg_Wout   = (const float*)d_in[12];
    const float* ckg_bout   = (const float*)d_in[13];
    const float* ckg_skip   = (const float*)d_in[14];
    const float* ckg_krel   = (const float*)d_in[15];
    const float* ckg_vrel   = (const float*)d_in[16];
    const float* ckg_prel   = (const float*)d_in[17];
    const float* psg_Wkqv   = (const float*)d_in[18];
    const float* psg_bkqv   = (const float*)d_in[19];
    const float* psg_Wout   = (const float*)d_in[20];
    const float* psg_bout   = (const float*)d_in[21];
    const float* psg_skip   = (const float*)d_in[22];
    const float* psg_krel   = (const float*)d_in[23];
    const float* psg_vrel   = (const float*)d_in[24];
    const float* psg_prel   = (const float*)d_in[25];
    const int* ei_d2g_src   = (const int*)d_in[26];
    const int* ei_d2g_dst   = (const int*)d_in[27];
    const int* ei_g2d_src   = (const int*)d_in[28];
    const int* ei_g2d_dst   = (const int*)d_in[29];
    const int* psg_src      = (const int*)d_in[30];
    const int* psg_dst      = (const int*)d_in[31];
    float* out = (float*)d_out;

    static int inited = 0;
    static float *p_x0, *p_x1, *p_px, *p_q0, *p_q1, *p_pq;
    static __half *p_kv0h, *p_kv1h, *p_pkvh;
    static float *p_agg0, *p_agg1, *p_pagg;
    static float *p_Wc, *p_pWc, *p_bc, *p_pbc, *p_vec;
    static int *p_deg0, *p_deg1, *p_degp, *p_roff0, *p_roff1, *p_roffp;
    static int *p_col0, *p_col1, *p_colp, *p_bs0, *p_bs1, *p_bsp;
    static cudaStream_t s1, s2;
    static cudaEvent_t evFork, evCsr, evWc, evOutP[2], evCsJ[2];
    if (!inited) {
        cudaGetSymbolAddress((void**)&p_x0, g_x0);
        cudaGetSymbolAddress((void**)&p_x1, g_x1);
        cudaGetSymbolAddress((void**)&p_px, g_px);
        cudaGetSymbolAddress((void**)&p_q0, g_q0);
        cudaGetSymbolAddress((void**)&p_q1, g_q1);
        cudaGetSymbolAddress((void**)&p_pq, g_pq);
        cudaGetSymbolAddress((void**)&p_kv0h, g_kv0h);
        cudaGetSymbolAddress((void**)&p_kv1h, g_kv1h);
        cudaGetSymbolAddress((void**)&p_pkvh, g_pkvh);
        cudaGetSymbolAddress((void**)&p_agg0, g_agg0);
        cudaGetSymbolAddress((void**)&p_agg1, g_agg1);
        cudaGetSymbolAddress((void**)&p_pagg, g_pagg);
        cudaGetSymbolAddress((void**)&p_Wc, g_Wc);
        cudaGetSymbolAddress((void**)&p_pWc, g_pWc);
        cudaGetSymbolAddress((void**)&p_bc, g_bc);
        cudaGetSymbolAddress((void**)&p_pbc, g_pbc);
        cudaGetSymbolAddress((void**)&p_vec, g_vec);
        cudaGetSymbolAddress((void**)&p_deg0, g_deg0);
        cudaGetSymbolAddress((void**)&p_deg1, g_deg1);
        cudaGetSymbolAddress((void**)&p_degp, g_degp);
        cudaGetSymbolAddress((void**)&p_roff0, g_roff0);
        cudaGetSymbolAddress((void**)&p_roff1, g_roff1);
        cudaGetSymbolAddress((void**)&p_roffp, g_roffp);
        cudaGetSymbolAddress((void**)&p_col0, g_col0);
        cudaGetSymbolAddress((void**)&p_col1, g_col1);
        cudaGetSymbolAddress((void**)&p_colp, g_colp);
        cudaGetSymbolAddress((void**)&p_bs0, g_bs0);
        cudaGetSymbolAddress((void**)&p_bs1, g_bs1);
        cudaGetSymbolAddress((void**)&p_bsp, g_bsp);
        cudaFuncSetAttribute(gemm_mma_k, cudaFuncAttributeMaxDynamicSharedMemorySize, SMEM_MMA);
        cudaStreamCreateWithFlags(&s1, cudaStreamNonBlocking);
        cudaStreamCreateWithFlags(&s2, cudaStreamNonBlocking);
        cudaEventCreateWithFlags(&evFork, cudaEventDisableTiming);
        cudaEventCreateWithFlags(&evCsr, cudaEventDisableTiming);
        cudaEventCreateWithFlags(&evWc, cudaEventDisableTiming);
        for (int i = 0; i < 2; i++) {
            cudaEventCreateWithFlags(&evOutP[i], cudaEventDisableTiming);
            cudaEventCreateWithFlags(&evCsJ[i], cudaEventDisableTiming);
        }
        inited = 1;
    }

    const int GB_CKG_M = (NCKG + 127) / 128;  // 391
    const int GB_PSG_M = (NPSG + 127) / 128;  // 79
    const int NB_CKG = (NCKG + 1023) / 1024;  // 49
    const int NB_PSG = (NPSG + 1023) / 1024;  // 10
    const int ETOT = 2 * ECKG + EPSG;         // 1.1M
    const float* FZ = nullptr;
    GemmJob JZ = {};

    // ---- fork: CSR chain on s1, weight builds on s2 ----
    cudaEventRecord(evFork, 0);
    cudaStreamWaitEvent(s1, evFork, 0);
    cudaStreamWaitEvent(s2, evFork, 0);

    // ---- s1: full CSR build chain ----
    cudaMemsetAsync(p_deg0, 0, NCKG * sizeof(int), s1);
    cudaMemsetAsync(p_deg1, 0, NCKG * sizeof(int), s1);
    cudaMemsetAsync(p_degp, 0, NPSG * sizeof(int), s1);
    hist3_k<<<(ETOT + 255) / 256, 256, 0, s1>>>(ei_d2g_dst, ei_g2d_dst, psg_dst,
                                                p_deg0, p_deg1, p_degp);
    scan1_k<<<dim3(NB_CKG, 3), 1024, 0, s1>>>(p_deg0, p_roff0, p_bs0, p_deg1, p_roff1, p_bs1,
                                              p_degp, p_roffp, p_bsp, NCKG, NPSG, NB_PSG);
    scan2all_k<<<3, 32, 0, s1>>>(p_bs0, NB_CKG, p_bs1, NB_CKG, p_bsp, NB_PSG);
    scan3_k<<<dim3(NB_CKG, 3), 1024, 0, s1>>>(p_roff0, p_bs0, p_deg0, p_roff1, p_bs1, p_deg1,
                                              p_roffp, p_bsp, p_degp, NCKG, NPSG, NB_CKG, NB_PSG);
    scatter3_k<<<(ETOT + 255) / 256, 256, 0, s1>>>(
        ei_d2g_src, ei_d2g_dst, p_roff0, p_deg0, p_col0,
        ei_g2d_src, ei_g2d_dst, p_roff1, p_deg1, p_col1,
        psg_src, psg_dst, p_roffp, p_degp, p_colp);
    cudaEventRecord(evCsr, s1);

    // ---- s2: all 5 combined-weight builds (PSG + 4 CKG) ----
    build_wc_all_k<<<dim3(384, 5), 128, 0, s2>>>(
        ckg_Wkqv, ckg_bkqv, ckg_krel, ckg_vrel, p_Wc, p_bc,
        psg_Wkqv, psg_bkqv, psg_krel, psg_vrel, p_pWc, p_pbc);
    cudaEventRecord(evWc, s2);

    // ---- s0 (capture stream): projections, concurrent with CSR + wc builds ----
    cudaMemsetAsync(p_vec, 0, 768 * sizeof(float));
    qv_k<<<1, 128>>>(query_emb, query_W, query_b, p_vec);
    {
        GemmJob a = {ckg_x_dis, ckg_lin_W, ckg_lin_b, p_x0, nullptr, nullptr, 0, NCKG};
        GemmJob b = {ckg_x_drug, ckg_lin_W + 128 * 128, ckg_lin_b + 128, p_x1, nullptr, nullptr, 0, NCKG};
        GemmJob c = {psg_x, psg_lin_W, psg_lin_b, p_px, nullptr, nullptr, 0, NPSG};
        gemm_mma_k<<<dim3(1, GB_CKG_M, 3), 256, SMEM_MMA>>>(a, b, c, 128, 1, FZ, FZ, FZ);
    }

    // ---- join wc builds before PSG qkv GEMM ----
    cudaStreamWaitEvent(0, evWc, 0);
    {
        GemmJob a = {p_px, p_pWc, p_pbc, p_pq, p_pkvh, nullptr, 0, NPSG};
        gemm_mma_k<<<dim3(3, GB_PSG_M, 1), 256, SMEM_MMA>>>(a, JZ, JZ, 384, 3, FZ, FZ, FZ);
    }

    // ---- join CSR before first edge pass ----
    cudaStreamWaitEvent(0, evCsr, 0);
    edge_agg_k<<<(NPSG * 32 + 255) / 256, 256>>>(p_pq, p_pkvh, p_roffp, p_colp,
                                                 psg_prel, p_pagg, NPSG);
    {
        GemmJob a = {p_pagg, psg_Wout, psg_bout, p_px, nullptr, p_px, 0, NPSG};
        gemm_mma_k<<<dim3(1, GB_PSG_M, 1), 256, SMEM_MMA>>>(a, JZ, JZ, 128, 2, psg_skip, FZ, FZ);
    }
    colsum2_k<<<dim3((NPSG + 511) / 512, 1), 256>>>(p_px, nullptr, NPSG, p_vec + 128);
    vecadd_k<<<1, 128>>>(p_vec, p_vec + 128, 1.0f / NPSG, p_vec + 256); // fused = qv + psg_ctx

    // ---- two think steps (Wc pre-built) ----
    const float* fused = p_vec + 256;
    for (int i = 0; i < 2; i++) {
        float* tsum = p_vec + 384 + i * 128;   // pre-zeroed in init memset
        const float* Wc0 = p_Wc + (size_t)(i * 2 + 0) * 128 * 384;
        const float* Wc1 = p_Wc + (size_t)(i * 2 + 1) * 128 * 384;
        const float* bc0 = p_bc + (size_t)(i * 2 + 0) * 384;
        const float* bc1 = p_bc + (size_t)(i * 2 + 1) * 384;

        {
            GemmJob a = {p_x0, Wc0, bc0, p_q0, p_kv0h, nullptr, 0, NCKG};
            GemmJob b = {p_x1, Wc1, bc1, p_q1, p_kv1h, nullptr, 0, NCKG};
            gemm_mma_k<<<dim3(3, GB_CKG_M, 2), 256, SMEM_MMA>>>(a, b, JZ, 384, 3, FZ, fused, FZ);
        }

        edge_agg2_k<<<(2 * NCKG * 32 + 255) / 256, 256>>>(
            p_q1, p_kv0h, p_roff0, p_col0, ckg_prel + i * 4 + 0, p_agg1,
            p_q0, p_kv1h, p_roff1, p_col1, ckg_prel + i * 4 + 2, p_agg0, NCKG);

        float* dst0 = (i == 0) ? p_x0 : out;
        float* dst1 = (i == 0) ? p_x1 : (out + (size_t)NCKG * 128);
        {
            GemmJob a = {p_agg0, ckg_Wout + (size_t)(i * 2 + 0) * 128 * 128,
                         ckg_bout + (i * 2 + 0) * 128, dst0, nullptr, p_x0, i * 2 + 0, NCKG};
            GemmJob b = {p_agg1, ckg_Wout + (size_t)(i * 2 + 1) * 128 * 128,
                         ckg_bout + (i * 2 + 1) * 128, dst1, nullptr, p_x1, i * 2 + 1, NCKG};
            gemm_mma_k<<<dim3(1, GB_CKG_M, 2), 256, SMEM_MMA>>>(a, b, JZ, 128, 2, ckg_skip,
                                                                FZ, fused);
        }

        // fork thought-vector reduction onto s2; step i+1 proceeds on s0 concurrently
        cudaEventRecord(evOutP[i], 0);
        cudaStreamWaitEvent(s2, evOutP[i], 0);
        colsum2_k<<<dim3((NCKG + 511) / 512, 2), 256, 0, s2>>>(dst0, dst1, NCKG, tsum);
        vecscale_k<<<1, 128, 0, s2>>>(tsum, 1.0f / (2 * NCKG),
                                      out + (size_t)2 * NCKG * 128 + i * 128);
        cudaEventRecord(evCsJ[i], s2);
    }

    // ---- join all forked work before capture ends ----
    cudaStreamWaitEvent(0, evCsJ[0], 0);
    cudaStreamWaitEvent(0, evCsJ[1], 0);
}